// round 1
// baseline (speedup 1.0000x reference)
#include <cuda_runtime.h>
#include <cuda_bf16.h>
#include <math.h>

// Problem constants
#define BATCH 2
#define SEQ   2048
#define EMB   2048
#define HEADS 16
#define DHEAD 128
#define DROPE 32
#define SPLIT 96
#define CLAT  512
#define NTOK  (BATCH*SEQ)          // 4096

// ---------------------------------------------------------------------------
// Scratch buffers (device globals; no allocation allowed)
// ---------------------------------------------------------------------------
__device__ float g_cq[NTOK * CLAT];        // c_q
__device__ float g_qr[NTOK * HEADS * DROPE];   // q_rot pre-rotary (4096x512)
__device__ float g_kr[NTOK * HEADS * DROPE];   // k_rot pre-rotary (4096x512)
__device__ float g_q [NTOK * HEADS * DHEAD];   // assembled Q  [tok][h*128+d]
__device__ float g_k [NTOK * HEADS * DHEAD];   // assembled K
__device__ float g_v [NTOK * HEADS * DHEAD];   // V
__device__ float g_ao[NTOK * HEADS * DHEAD];   // attention output

// ---------------------------------------------------------------------------
// Generic fp32 GEMM + bias: C[M,N] = A[M,K] * B[K,N] + bias[N]
// Output column remap: out_col = (n/seg)*hstride + (n%seg) + col_off
// (plain write: seg=N, hstride=N, col_off=0, out_stride=N)
// BM=128, BN=64, BK=16, 256 threads, 8x4 per-thread tile.
// ---------------------------------------------------------------------------
#define GBM 128
#define GBN 64
#define GBK 16

__global__ __launch_bounds__(256)
void gemm_bias_kernel(const float* __restrict__ A, const float* __restrict__ B,
                      const float* __restrict__ bias, float* __restrict__ Cout,
                      int M, int N, int K,
                      int seg, int hstride, int col_off, int out_stride)
{
    __shared__ float As[GBK][GBM + 4];
    __shared__ float Bs[GBK][GBN];

    const int t  = threadIdx.x;
    const int tx = t & 15;        // N direction (4 cols each)
    const int ty = t >> 4;        // M direction (8 rows each)
    const int m0 = blockIdx.y * GBM;
    const int n0 = blockIdx.x * GBN;

    float acc[8][4];
#pragma unroll
    for (int i = 0; i < 8; i++)
#pragma unroll
        for (int j = 0; j < 4; j++) acc[i][j] = 0.f;

    for (int kk = 0; kk < K; kk += GBK) {
        // Load A tile (128x16) transposed into As[k][m]
#pragma unroll
        for (int i = 0; i < 2; i++) {
            int f   = t + i * 256;          // 0..511 float4s
            int row = f >> 2;               // 0..127
            int kc  = (f & 3) * 4;          // 0,4,8,12
            float4 a = *(const float4*)&A[(size_t)(m0 + row) * K + kk + kc];
            As[kc + 0][row] = a.x;
            As[kc + 1][row] = a.y;
            As[kc + 2][row] = a.z;
            As[kc + 3][row] = a.w;
        }
        // Load B tile (16x64)
        {
            int row = t >> 4;               // 0..15
            int nc  = (t & 15) * 4;         // 0..60
            float4 b = *(const float4*)&B[(size_t)(kk + row) * N + n0 + nc];
            *(float4*)&Bs[row][nc] = b;
        }
        __syncthreads();

#pragma unroll
        for (int k = 0; k < GBK; k++) {
            float4 b4 = *(const float4*)&Bs[k][tx * 4];
            float4 a0 = *(const float4*)&As[k][ty * 8];
            float4 a1 = *(const float4*)&As[k][ty * 8 + 4];
            float av[8] = {a0.x, a0.y, a0.z, a0.w, a1.x, a1.y, a1.z, a1.w};
            float bv[4] = {b4.x, b4.y, b4.z, b4.w};
#pragma unroll
            for (int i = 0; i < 8; i++)
#pragma unroll
                for (int j = 0; j < 4; j++)
                    acc[i][j] += av[i] * bv[j];
        }
        __syncthreads();
    }

#pragma unroll
    for (int i = 0; i < 8; i++) {
        int m = m0 + ty * 8 + i;
#pragma unroll
        for (int j = 0; j < 4; j++) {
            int n = n0 + tx * 4 + j;
            float val = acc[i][j] + bias[n];
            int oc = (n / seg) * hstride + (n % seg) + col_off;
            Cout[(size_t)m * out_stride + oc] = val;
        }
    }
}

// ---------------------------------------------------------------------------
// Rotary kernel: apply rotary to q_rot / k_rot (only first 16 of 32 dims
// rotate; dims 16..31 pass through). Writes into assembled Q/K at col
// offset h*128+96, and k_rot into its output region.
// One thread per (token, head).
// ---------------------------------------------------------------------------
__global__ void rotary_kernel(const float* __restrict__ qr,
                              const float* __restrict__ kr,
                              float* __restrict__ qout,
                              float* __restrict__ kout,
                              float* __restrict__ krot_out)
{
    int idx = blockIdx.x * blockDim.x + threadIdx.x;   // tok*16 + h
    if (idx >= NTOK * HEADS) return;
    int h   = idx & (HEADS - 1);
    int tok = idx >> 4;
    int s   = tok & (SEQ - 1);
    float tpos = (float)s / 40.0f;

    float xq[32], xk[32];
#pragma unroll
    for (int i = 0; i < 8; i++) {
        float4 a = *(const float4*)&qr[(size_t)idx * 32 + i * 4];
        xq[i*4+0]=a.x; xq[i*4+1]=a.y; xq[i*4+2]=a.z; xq[i*4+3]=a.w;
        float4 b = *(const float4*)&kr[(size_t)idx * 32 + i * 4];
        xk[i*4+0]=b.x; xk[i*4+1]=b.y; xk[i*4+2]=b.z; xk[i*4+3]=b.w;
    }

    float yq[32], yk[32];
    // log2(10000)/8 = 1.660964...
#pragma unroll
    for (int j = 0; j < 8; j++) {
        float invf = exp2f(-1.6609640474436813f * (float)j);
        float ang = tpos * invf;
        float sj, cj;
        sincosf(ang, &sj, &cj);
        yq[j]     = xq[j] * cj - xq[j + 8] * sj;
        yq[j + 8] = xq[j + 8] * cj + xq[j] * sj;
        yk[j]     = xk[j] * cj - xk[j + 8] * sj;
        yk[j + 8] = xk[j + 8] * cj + xk[j] * sj;
    }
#pragma unroll
    for (int d = 16; d < 32; d++) { yq[d] = xq[d]; yk[d] = xk[d]; }

    size_t obase = (size_t)tok * (HEADS * DHEAD) + h * DHEAD + SPLIT;
#pragma unroll
    for (int i = 0; i < 8; i++) {
        float4 a = make_float4(yq[i*4], yq[i*4+1], yq[i*4+2], yq[i*4+3]);
        *(float4*)&qout[obase + i * 4] = a;
        float4 b = make_float4(yk[i*4], yk[i*4+1], yk[i*4+2], yk[i*4+3]);
        *(float4*)&kout[obase + i * 4] = b;
        *(float4*)&krot_out[(size_t)idx * 32 + i * 4] = b;
    }
}

// ---------------------------------------------------------------------------
// Causal flash-attention, fp32. BLOCK_M=BLOCK_N=64, D=128, 256 threads.
// Grid: (SEQ/64, B*H). Online softmax, transposed smem tiles for float4
// fragment loads.
// ---------------------------------------------------------------------------
#define FM 64
#define FN 64
#define FD 128
// smem layout (floats):
#define OFF_QT 0                     // Qt[128][64]
#define OFF_KT (OFF_QT + FD*FM)      // Kt[128][64]
#define OFF_VS (OFF_KT + FD*FN)      // Vs[64][132]
#define OFF_PT (OFF_VS + FN*132)     // Pt[64][68]
#define SMEM_FLOATS (OFF_PT + FN*68)

__global__ __launch_bounds__(256)
void attn_kernel(const float* __restrict__ q, const float* __restrict__ k,
                 const float* __restrict__ v, float* __restrict__ out)
{
    extern __shared__ float sm[];
    float* Qt = sm + OFF_QT;
    float* Kt = sm + OFF_KT;
    float* Vs = sm + OFF_VS;
    float* Pt = sm + OFF_PT;

    const int t  = threadIdx.x;
    const int tx = t & 15;
    const int ty = t >> 4;
    const int bh = blockIdx.y;
    const int b  = bh >> 4;
    const int h  = bh & 15;
    const int q0 = blockIdx.x * FM;

    const float scale = 0.08838834764831845f;  // 1/sqrt(128)

    // Load Q tile, scaled, transposed Qt[d][m]
#pragma unroll
    for (int i = 0; i < 8; i++) {
        int f  = t + i * 256;       // 0..2047 float4s
        int m  = f >> 5;            // 0..63
        int dc = (f & 31) * 4;
        float4 qv = *(const float4*)&q[((size_t)((b * SEQ + q0 + m) * HEADS + h)) * FD + dc];
        Qt[(dc + 0) * FM + m] = qv.x * scale;
        Qt[(dc + 1) * FM + m] = qv.y * scale;
        Qt[(dc + 2) * FM + m] = qv.z * scale;
        Qt[(dc + 3) * FM + m] = qv.w * scale;
    }

    float mrow[4], lrow[4], o[4][8];
#pragma unroll
    for (int i = 0; i < 4; i++) { mrow[i] = -INFINITY; lrow[i] = 0.f; }
#pragma unroll
    for (int i = 0; i < 4; i++)
#pragma unroll
        for (int j = 0; j < 8; j++) o[i][j] = 0.f;

    const int ntiles = q0 / FN + 1;
    for (int nt = 0; nt < ntiles; nt++) {
        const int n0 = nt * FN;
        __syncthreads();   // prior PV done before overwriting tiles
        // Load K (transposed) and V tiles
#pragma unroll
        for (int i = 0; i < 8; i++) {
            int f  = t + i * 256;
            int m  = f >> 5;
            int dc = (f & 31) * 4;
            size_t gidx = ((size_t)((b * SEQ + n0 + m) * HEADS + h)) * FD + dc;
            float4 kv = *(const float4*)&k[gidx];
            Kt[(dc + 0) * FN + m] = kv.x;
            Kt[(dc + 1) * FN + m] = kv.y;
            Kt[(dc + 2) * FN + m] = kv.z;
            Kt[(dc + 3) * FN + m] = kv.w;
            float4 vv = *(const float4*)&v[gidx];
            *(float4*)&Vs[m * 132 + dc] = vv;
        }
        __syncthreads();

        // Scores S = Qt^T Kt  (each thread 4x4)
        float s[4][4];
#pragma unroll
        for (int i = 0; i < 4; i++)
#pragma unroll
            for (int j = 0; j < 4; j++) s[i][j] = 0.f;

#pragma unroll 4
        for (int d = 0; d < FD; d++) {
            float4 qa = *(const float4*)&Qt[d * FM + ty * 4];
            float4 ka = *(const float4*)&Kt[d * FN + tx * 4];
            float av[4] = {qa.x, qa.y, qa.z, qa.w};
            float bv[4] = {ka.x, ka.y, ka.z, ka.w};
#pragma unroll
            for (int i = 0; i < 4; i++)
#pragma unroll
                for (int j = 0; j < 4; j++)
                    s[i][j] += av[i] * bv[j];
        }

        // Causal mask (only diagonal tile)
        if (n0 == q0) {
#pragma unroll
            for (int i = 0; i < 4; i++) {
                int row = ty * 4 + i;
#pragma unroll
                for (int j = 0; j < 4; j++) {
                    int col = tx * 4 + j;
                    if (col > row) s[i][j] = -INFINITY;
                }
            }
        }

        // Online softmax update
#pragma unroll
        for (int i = 0; i < 4; i++) {
            float rm = fmaxf(fmaxf(s[i][0], s[i][1]), fmaxf(s[i][2], s[i][3]));
            rm = fmaxf(rm, __shfl_xor_sync(0xffffffffu, rm, 1));
            rm = fmaxf(rm, __shfl_xor_sync(0xffffffffu, rm, 2));
            rm = fmaxf(rm, __shfl_xor_sync(0xffffffffu, rm, 4));
            rm = fmaxf(rm, __shfl_xor_sync(0xffffffffu, rm, 8));
            float mnew = fmaxf(mrow[i], rm);
            float corr = __expf(mrow[i] - mnew);
            float rs = 0.f;
#pragma unroll
            for (int j = 0; j < 4; j++) {
                float p = __expf(s[i][j] - mnew);
                s[i][j] = p;
                rs += p;
            }
            rs += __shfl_xor_sync(0xffffffffu, rs, 1);
            rs += __shfl_xor_sync(0xffffffffu, rs, 2);
            rs += __shfl_xor_sync(0xffffffffu, rs, 4);
            rs += __shfl_xor_sync(0xffffffffu, rs, 8);
            lrow[i] = lrow[i] * corr + rs;
            mrow[i] = mnew;
#pragma unroll
            for (int j = 0; j < 8; j++) o[i][j] *= corr;
        }

        // Store P transposed: Pt[key][m]
#pragma unroll
        for (int i = 0; i < 4; i++)
#pragma unroll
            for (int j = 0; j < 4; j++)
                Pt[(tx * 4 + j) * 68 + ty * 4 + i] = s[i][j];
        __syncthreads();

        // O += P * V  (each thread 4 rows x 8 head-dims)
#pragma unroll 4
        for (int kk = 0; kk < FN; kk++) {
            float4 pm = *(const float4*)&Pt[kk * 68 + ty * 4];
            float pv[4] = {pm.x, pm.y, pm.z, pm.w};
            float4 va = *(const float4*)&Vs[kk * 132 + tx * 8];
            float4 vb = *(const float4*)&Vs[kk * 132 + tx * 8 + 4];
            float vv[8] = {va.x, va.y, va.z, va.w, vb.x, vb.y, vb.z, vb.w};
#pragma unroll
            for (int i = 0; i < 4; i++)
#pragma unroll
                for (int j = 0; j < 8; j++)
                    o[i][j] += pv[i] * vv[j];
        }
    }

    // Epilogue
#pragma unroll
    for (int i = 0; i < 4; i++) {
        float inv = 1.0f / lrow[i];
        size_t row = (size_t)(b * SEQ + q0 + ty * 4 + i);
        float4 w0 = make_float4(o[i][0]*inv, o[i][1]*inv, o[i][2]*inv, o[i][3]*inv);
        float4 w1 = make_float4(o[i][4]*inv, o[i][5]*inv, o[i][6]*inv, o[i][7]*inv);
        *(float4*)&out[row * (HEADS * DHEAD) + h * DHEAD + tx * 8]     = w0;
        *(float4*)&out[row * (HEADS * DHEAD) + h * DHEAD + tx * 8 + 4] = w1;
    }
}

// ---------------------------------------------------------------------------
// Launcher
// ---------------------------------------------------------------------------
extern "C" void kernel_launch(void* const* d_in, const int* in_sizes, int n_in,
                              void* d_out, int out_size)
{
    (void)in_sizes; (void)n_in; (void)out_size;

    const float* h_in   = (const float*)d_in[0];
    const float* W_dkv  = (const float*)d_in[1];
    const float* b_dkv  = (const float*)d_in[2];
    const float* W_dq   = (const float*)d_in[3];
    const float* b_dq   = (const float*)d_in[4];
    const float* W_uk   = (const float*)d_in[5];
    const float* b_uk   = (const float*)d_in[6];
    const float* W_uv   = (const float*)d_in[7];
    const float* b_uv   = (const float*)d_in[8];
    const float* W_uq   = (const float*)d_in[9];
    const float* b_uq   = (const float*)d_in[10];
    const float* W_qr   = (const float*)d_in[11];
    const float* b_qr   = (const float*)d_in[12];
    const float* W_kr   = (const float*)d_in[13];
    const float* b_kr   = (const float*)d_in[14];
    const float* W_out  = (const float*)d_in[15];
    const float* b_out  = (const float*)d_in[16];

    float* out_main = (float*)d_out;                                   // B*S*E
    float* out_ckv  = out_main + (size_t)NTOK * EMB;                   // B*S*C
    float* out_krot = out_ckv + (size_t)NTOK * CLAT;                   // B*S*H*32

    float *p_cq, *p_qr, *p_kr, *p_q, *p_k, *p_v, *p_ao;
    cudaGetSymbolAddress((void**)&p_cq, g_cq);
    cudaGetSymbolAddress((void**)&p_qr, g_qr);
    cudaGetSymbolAddress((void**)&p_kr, g_kr);
    cudaGetSymbolAddress((void**)&p_q,  g_q);
    cudaGetSymbolAddress((void**)&p_k,  g_k);
    cudaGetSymbolAddress((void**)&p_v,  g_v);
    cudaGetSymbolAddress((void**)&p_ao, g_ao);

    dim3 thr(256);
    const int M = NTOK;

    // 1. c_kv = h @ W_dkv  -> directly to output region
    gemm_bias_kernel<<<dim3(CLAT/GBN, M/GBM), thr>>>(h_in, W_dkv, b_dkv, out_ckv,
        M, CLAT, EMB, CLAT, CLAT, 0, CLAT);
    // 2. c_q = h @ W_dq
    gemm_bias_kernel<<<dim3(CLAT/GBN, M/GBM), thr>>>(h_in, W_dq, b_dq, p_cq,
        M, CLAT, EMB, CLAT, CLAT, 0, CLAT);
    // 3. k_rot_pre = h @ W_kr
    gemm_bias_kernel<<<dim3((HEADS*DROPE)/GBN, M/GBM), thr>>>(h_in, W_kr, b_kr, p_kr,
        M, HEADS*DROPE, EMB, HEADS*DROPE, HEADS*DROPE, 0, HEADS*DROPE);
    // 4. k_base = c_kv @ W_uk -> assembled K (cols h*128 + 0..95)
    gemm_bias_kernel<<<dim3((HEADS*SPLIT)/GBN, M/GBM), thr>>>(out_ckv, W_uk, b_uk, p_k,
        M, HEADS*SPLIT, CLAT, SPLIT, DHEAD, 0, HEADS*DHEAD);
    // 5. v = c_kv @ W_uv (plain [tok][h*128+d])
    gemm_bias_kernel<<<dim3((HEADS*DHEAD)/GBN, M/GBM), thr>>>(out_ckv, W_uv, b_uv, p_v,
        M, HEADS*DHEAD, CLAT, HEADS*DHEAD, HEADS*DHEAD, 0, HEADS*DHEAD);
    // 6. q_base = c_q @ W_uq -> assembled Q
    gemm_bias_kernel<<<dim3((HEADS*SPLIT)/GBN, M/GBM), thr>>>(p_cq, W_uq, b_uq, p_q,
        M, HEADS*SPLIT, CLAT, SPLIT, DHEAD, 0, HEADS*DHEAD);
    // 7. q_rot_pre = c_q @ W_qr
    gemm_bias_kernel<<<dim3((HEADS*DROPE)/GBN, M/GBM), thr>>>(p_cq, W_qr, b_qr, p_qr,
        M, HEADS*DROPE, CLAT, HEADS*DROPE, HEADS*DROPE, 0, HEADS*DROPE);
    // 8. rotary: fills Q/K cols 96..127 and k_rot output
    rotary_kernel<<<(NTOK*HEADS + 255)/256, 256>>>(p_qr, p_kr, p_q, p_k, out_krot);
    // 9. attention
    {
        size_t smem_bytes = (size_t)SMEM_FLOATS * sizeof(float);
        cudaFuncSetAttribute(attn_kernel, cudaFuncAttributeMaxDynamicSharedMemorySize,
                             (int)smem_bytes);
        attn_kernel<<<dim3(SEQ/FM, BATCH*HEADS), thr, smem_bytes>>>(p_q, p_k, p_v, p_ao);
    }
    // 10. out = attn_out @ W_out + b_out
    gemm_bias_kernel<<<dim3(EMB/GBN, M/GBM), thr>>>(p_ao, W_out, b_out, out_main,
        M, EMB, HEADS*DHEAD, EMB, EMB, 0, EMB);
}

// round 3
// speedup vs baseline: 1.4358x; 1.4358x over previous
#include <cuda_runtime.h>
#include <cuda_bf16.h>
#include <math.h>
#include <cstdint>

// Problem constants
#define BATCH 2
#define SEQ   2048
#define EMB   2048
#define HEADS 16
#define DHEAD 128
#define DROPE 32
#define SPLIT 96
#define CLAT  512
#define NTOK  (BATCH*SEQ)          // 4096

// ---------------------------------------------------------------------------
// Scratch buffers (device globals; no allocation allowed)
// ---------------------------------------------------------------------------
__device__ float g_cq[NTOK * CLAT];
__device__ float g_qr[NTOK * HEADS * DROPE];
__device__ float g_kr[NTOK * HEADS * DROPE];
__device__ float g_q [NTOK * HEADS * DHEAD];
__device__ float g_k [NTOK * HEADS * DHEAD];
__device__ float g_v [NTOK * HEADS * DHEAD];
__device__ float g_ao[NTOK * HEADS * DHEAD];

// ---------------------------------------------------------------------------
// Helpers
// ---------------------------------------------------------------------------
__device__ __forceinline__ uint32_t smem_u32(const void* p) {
    uint32_t a;
    asm("{ .reg .u64 t; cvta.to.shared.u64 t, %1; cvt.u32.u64 %0, t; }"
        : "=r"(a) : "l"(p));
    return a;
}

// pack two floats to bf16x2: lo_elem -> low half, hi_elem -> high half
__device__ __forceinline__ uint32_t packbf(float lo_elem, float hi_elem) {
    uint32_t r;
    asm("cvt.rn.bf16x2.f32 %0, %1, %2;" : "=r"(r) : "f"(hi_elem), "f"(lo_elem));
    return r;
}
__device__ __forceinline__ float bf16rt(float x) {   // round-trip through bf16
    __nv_bfloat16 h = __float2bfloat16(x);
    return __bfloat162float(h);
}

__device__ __forceinline__ void ldsm_x4(uint32_t& r0, uint32_t& r1, uint32_t& r2,
                                        uint32_t& r3, uint32_t addr) {
    asm volatile("ldmatrix.sync.aligned.m8n8.x4.shared.b16 {%0,%1,%2,%3}, [%4];"
                 : "=r"(r0), "=r"(r1), "=r"(r2), "=r"(r3) : "r"(addr));
}
__device__ __forceinline__ void ldsm_x4t(uint32_t& r0, uint32_t& r1, uint32_t& r2,
                                         uint32_t& r3, uint32_t addr) {
    asm volatile("ldmatrix.sync.aligned.m8n8.x4.trans.shared.b16 {%0,%1,%2,%3}, [%4];"
                 : "=r"(r0), "=r"(r1), "=r"(r2), "=r"(r3) : "r"(addr));
}

__device__ __forceinline__ void mma_bf16(float* d, const uint32_t* a, const uint32_t* b) {
    asm volatile(
        "mma.sync.aligned.m16n8k16.row.col.f32.bf16.bf16.f32 "
        "{%0,%1,%2,%3}, {%4,%5,%6,%7}, {%8,%9}, {%0,%1,%2,%3};"
        : "+f"(d[0]), "+f"(d[1]), "+f"(d[2]), "+f"(d[3])
        : "r"(a[0]), "r"(a[1]), "r"(a[2]), "r"(a[3]), "r"(b[0]), "r"(b[1]));
}

// ---------------------------------------------------------------------------
// 3xBF16 mma.sync GEMM + bias: C[M,N] = A[M,K] * B[K,N] + bias[N]
// Tile 128x128x32, double buffered. 8 warps (2m x 4n), warp tile 64x32.
// Output col remap: oc = (n/seg)*hstride + n%seg + col_off
// ---------------------------------------------------------------------------
#define BM 128
#define BN 128
#define BK 32
#define PA 40                      // A smem pitch (halves)
#define PB 136                     // B smem pitch (halves)
#define A_PLANE 10240              // 128*40*2 bytes
#define B_PLANE 8704               // 32*136*2 bytes
#define OFF_AHI 0
#define OFF_ALO (A_PLANE)
#define OFF_BHI (2*A_PLANE)
#define OFF_BLO (2*A_PLANE + B_PLANE)
#define SBUF    (2*A_PLANE + 2*B_PLANE)   // 37888
#define GSMEM   (2*SBUF)                  // 75776

__global__ __launch_bounds__(256, 1)
void mma_gemm_kernel(const float* __restrict__ A, const float* __restrict__ B,
                     const float* __restrict__ bias, float* __restrict__ C,
                     int M, int N, int K,
                     int seg, int hstride, int col_off, int ostride)
{
    extern __shared__ char smc[];
    const uint32_t sb = smem_u32(smc);
    const int t    = threadIdx.x;
    const int lane = t & 31;
    const int w    = t >> 5;
    const int m0   = blockIdx.y * BM;
    const int n0   = blockIdx.x * BN;
    const int wm   = (w >> 2) * 64;      // warp m offset in tile
    const int wn   = (w & 3) * 32;       // warp n offset in tile

    float acc[4][4][4];
#pragma unroll
    for (int i = 0; i < 4; i++)
#pragma unroll
        for (int j = 0; j < 4; j++)
#pragma unroll
            for (int r = 0; r < 4; r++) acc[i][j][r] = 0.f;

    // per-lane ldmatrix base offsets (bytes, within plane)
    const uint32_t aLane = (uint32_t)((wm + (lane & 15)) * PA + (lane >> 4) * 8) * 2;
    const uint32_t bLaneRow = (uint32_t)(lane & 15) * PB * 2;
    const uint32_t bLaneCol = (uint32_t)(wn + (lane >> 4) * 8) * 2;

    const int NC = K / BK;
    float4 pa[4], pb[4];

    // --- load + store chunk 0 into buffer 0 ---
    {
        const int kk = 0;
#pragma unroll
        for (int i = 0; i < 4; i++) {
            int f = t + i * 256;
            pa[i] = *(const float4*)&A[(size_t)(m0 + (f >> 3)) * K + kk + (f & 7) * 4];
        }
#pragma unroll
        for (int i = 0; i < 4; i++) {
            int f = t + i * 256;
            pb[i] = *(const float4*)&B[(size_t)(kk + (f >> 5)) * N + n0 + (f & 31) * 4];
        }
        char* buf = smc;
#pragma unroll
        for (int i = 0; i < 4; i++) {
            int f = t + i * 256;
            uint32_t off = (uint32_t)((f >> 3) * PA + (f & 7) * 4) * 2;
            float h0 = bf16rt(pa[i].x), h1 = bf16rt(pa[i].y);
            float h2 = bf16rt(pa[i].z), h3 = bf16rt(pa[i].w);
            *(uint32_t*)(buf + OFF_AHI + off)     = packbf(h0, h1);
            *(uint32_t*)(buf + OFF_AHI + off + 4) = packbf(h2, h3);
            *(uint32_t*)(buf + OFF_ALO + off)     = packbf(pa[i].x - h0, pa[i].y - h1);
            *(uint32_t*)(buf + OFF_ALO + off + 4) = packbf(pa[i].z - h2, pa[i].w - h3);
        }
#pragma unroll
        for (int i = 0; i < 4; i++) {
            int f = t + i * 256;
            uint32_t off = (uint32_t)((f >> 5) * PB + (f & 31) * 4) * 2;
            float h0 = bf16rt(pb[i].x), h1 = bf16rt(pb[i].y);
            float h2 = bf16rt(pb[i].z), h3 = bf16rt(pb[i].w);
            *(uint32_t*)(buf + OFF_BHI + off)     = packbf(h0, h1);
            *(uint32_t*)(buf + OFF_BHI + off + 4) = packbf(h2, h3);
            *(uint32_t*)(buf + OFF_BLO + off)     = packbf(pb[i].x - h0, pb[i].y - h1);
            *(uint32_t*)(buf + OFF_BLO + off + 4) = packbf(pb[i].z - h2, pb[i].w - h3);
        }
    }
    __syncthreads();

    for (int ch = 0; ch < NC; ch++) {
        const int p = ch & 1;
        const uint32_t base = sb + (uint32_t)p * SBUF;

        // prefetch next chunk (global -> regs)
        if (ch + 1 < NC) {
            const int kk = (ch + 1) * BK;
#pragma unroll
            for (int i = 0; i < 4; i++) {
                int f = t + i * 256;
                pa[i] = *(const float4*)&A[(size_t)(m0 + (f >> 3)) * K + kk + (f & 7) * 4];
            }
#pragma unroll
            for (int i = 0; i < 4; i++) {
                int f = t + i * 256;
                pb[i] = *(const float4*)&B[(size_t)(kk + (f >> 5)) * N + n0 + (f & 31) * 4];
            }
        }

        // MMA over current buffer: 2 k-steps of 16
#pragma unroll
        for (int ks = 0; ks < 2; ks++) {
            uint32_t Ah[4][4], Al[4][4], Bh[2][4], Bl[2][4];
            const uint32_t aOff = aLane + (uint32_t)ks * 32;          // +16 halves
            const uint32_t bOff = bLaneRow + (uint32_t)ks * (16 * PB * 2);
#pragma unroll
            for (int mt = 0; mt < 4; mt++) {
                uint32_t ad = base + aOff + (uint32_t)mt * (16 * PA * 2);
                ldsm_x4(Ah[mt][0], Ah[mt][1], Ah[mt][2], Ah[mt][3], ad + OFF_AHI);
                ldsm_x4(Al[mt][0], Al[mt][1], Al[mt][2], Al[mt][3], ad + OFF_ALO);
            }
#pragma unroll
            for (int np = 0; np < 2; np++) {
                uint32_t bd = base + bOff + bLaneCol + (uint32_t)np * 32;  // +16 halves
                ldsm_x4t(Bh[np][0], Bh[np][1], Bh[np][2], Bh[np][3], bd + OFF_BHI);
                ldsm_x4t(Bl[np][0], Bl[np][1], Bl[np][2], Bl[np][3], bd + OFF_BLO);
            }
#pragma unroll
            for (int mt = 0; mt < 4; mt++) {
#pragma unroll
                for (int nt = 0; nt < 4; nt++) {
                    const uint32_t* bh = &Bh[nt >> 1][(nt & 1) * 2];
                    const uint32_t* bl = &Bl[nt >> 1][(nt & 1) * 2];
                    mma_bf16(acc[mt][nt], Ah[mt], bh);
                    mma_bf16(acc[mt][nt], Ah[mt], bl);
                    mma_bf16(acc[mt][nt], Al[mt], bh);
                }
            }
        }

        // store prefetched chunk into the other buffer
        if (ch + 1 < NC) {
            char* buf = smc + (p ^ 1) * SBUF;
#pragma unroll
            for (int i = 0; i < 4; i++) {
                int f = t + i * 256;
                uint32_t off = (uint32_t)((f >> 3) * PA + (f & 7) * 4) * 2;
                float h0 = bf16rt(pa[i].x), h1 = bf16rt(pa[i].y);
                float h2 = bf16rt(pa[i].z), h3 = bf16rt(pa[i].w);
                *(uint32_t*)(buf + OFF_AHI + off)     = packbf(h0, h1);
                *(uint32_t*)(buf + OFF_AHI + off + 4) = packbf(h2, h3);
                *(uint32_t*)(buf + OFF_ALO + off)     = packbf(pa[i].x - h0, pa[i].y - h1);
                *(uint32_t*)(buf + OFF_ALO + off + 4) = packbf(pa[i].z - h2, pa[i].w - h3);
            }
#pragma unroll
            for (int i = 0; i < 4; i++) {
                int f = t + i * 256;
                uint32_t off = (uint32_t)((f >> 5) * PB + (f & 31) * 4) * 2;
                float h0 = bf16rt(pb[i].x), h1 = bf16rt(pb[i].y);
                float h2 = bf16rt(pb[i].z), h3 = bf16rt(pb[i].w);
                *(uint32_t*)(buf + OFF_BHI + off)     = packbf(h0, h1);
                *(uint32_t*)(buf + OFF_BHI + off + 4) = packbf(h2, h3);
                *(uint32_t*)(buf + OFF_BLO + off)     = packbf(pb[i].x - h0, pb[i].y - h1);
                *(uint32_t*)(buf + OFF_BLO + off + 4) = packbf(pb[i].z - h2, pb[i].w - h3);
            }
        }
        __syncthreads();
    }

    // Epilogue: direct float2 stores with bias + column remap
    const int r0 = lane >> 2;
    const int c0 = (lane & 3) * 2;
#pragma unroll
    for (int mt = 0; mt < 4; mt++) {
#pragma unroll
        for (int nt = 0; nt < 4; nt++) {
            int n = n0 + wn + nt * 8 + c0;
            int oc = (n / seg) * hstride + (n % seg) + col_off;
            float b0 = bias[n], b1 = bias[n + 1];
            int mrow0 = m0 + wm + mt * 16 + r0;
            float2 v0 = make_float2(acc[mt][nt][0] + b0, acc[mt][nt][1] + b1);
            *(float2*)&C[(size_t)mrow0 * ostride + oc] = v0;
            float2 v1 = make_float2(acc[mt][nt][2] + b0, acc[mt][nt][3] + b1);
            *(float2*)&C[(size_t)(mrow0 + 8) * ostride + oc] = v1;
        }
    }
}

// ---------------------------------------------------------------------------
// Rotary kernel (unchanged)
// ---------------------------------------------------------------------------
__global__ void rotary_kernel(const float* __restrict__ qr,
                              const float* __restrict__ kr,
                              float* __restrict__ qout,
                              float* __restrict__ kout,
                              float* __restrict__ krot_out)
{
    int idx = blockIdx.x * blockDim.x + threadIdx.x;
    if (idx >= NTOK * HEADS) return;
    int h   = idx & (HEADS - 1);
    int tok = idx >> 4;
    int s   = tok & (SEQ - 1);
    float tpos = (float)s / 40.0f;

    float xq[32], xk[32];
#pragma unroll
    for (int i = 0; i < 8; i++) {
        float4 a = *(const float4*)&qr[(size_t)idx * 32 + i * 4];
        xq[i*4+0]=a.x; xq[i*4+1]=a.y; xq[i*4+2]=a.z; xq[i*4+3]=a.w;
        float4 b = *(const float4*)&kr[(size_t)idx * 32 + i * 4];
        xk[i*4+0]=b.x; xk[i*4+1]=b.y; xk[i*4+2]=b.z; xk[i*4+3]=b.w;
    }

    float yq[32], yk[32];
#pragma unroll
    for (int j = 0; j < 8; j++) {
        float invf = exp2f(-1.6609640474436813f * (float)j);
        float ang = tpos * invf;
        float sj, cj;
        sincosf(ang, &sj, &cj);
        yq[j]     = xq[j] * cj - xq[j + 8] * sj;
        yq[j + 8] = xq[j + 8] * cj + xq[j] * sj;
        yk[j]     = xk[j] * cj - xk[j + 8] * sj;
        yk[j + 8] = xk[j + 8] * cj + xk[j] * sj;
    }
#pragma unroll
    for (int d = 16; d < 32; d++) { yq[d] = xq[d]; yk[d] = xk[d]; }

    size_t obase = (size_t)tok * (HEADS * DHEAD) + h * DHEAD + SPLIT;
#pragma unroll
    for (int i = 0; i < 8; i++) {
        float4 a = make_float4(yq[i*4], yq[i*4+1], yq[i*4+2], yq[i*4+3]);
        *(float4*)&qout[obase + i * 4] = a;
        float4 b = make_float4(yk[i*4], yk[i*4+1], yk[i*4+2], yk[i*4+3]);
        *(float4*)&kout[obase + i * 4] = b;
        *(float4*)&krot_out[(size_t)idx * 32 + i * 4] = b;
    }
}

// ---------------------------------------------------------------------------
// Causal flash-attention, fp32 (unchanged from round 1)
// ---------------------------------------------------------------------------
#define FM 64
#define FN 64
#define FD 128
#define OFF_QT 0
#define OFF_KT (OFF_QT + FD*FM)
#define OFF_VS (OFF_KT + FD*FN)
#define OFF_PT (OFF_VS + FN*132)
#define SMEM_FLOATS (OFF_PT + FN*68)

__global__ __launch_bounds__(256)
void attn_kernel(const float* __restrict__ q, const float* __restrict__ k,
                 const float* __restrict__ v, float* __restrict__ out)
{
    extern __shared__ float sm[];
    float* Qt = sm + OFF_QT;
    float* Kt = sm + OFF_KT;
    float* Vs = sm + OFF_VS;
    float* Pt = sm + OFF_PT;

    const int t  = threadIdx.x;
    const int tx = t & 15;
    const int ty = t >> 4;
    const int bh = blockIdx.y;
    const int b  = bh >> 4;
    const int h  = bh & 15;
    const int q0 = blockIdx.x * FM;

    const float scale = 0.08838834764831845f;

#pragma unroll
    for (int i = 0; i < 8; i++) {
        int f  = t + i * 256;
        int m  = f >> 5;
        int dc = (f & 31) * 4;
        float4 qv = *(const float4*)&q[((size_t)((b * SEQ + q0 + m) * HEADS + h)) * FD + dc];
        Qt[(dc + 0) * FM + m] = qv.x * scale;
        Qt[(dc + 1) * FM + m] = qv.y * scale;
        Qt[(dc + 2) * FM + m] = qv.z * scale;
        Qt[(dc + 3) * FM + m] = qv.w * scale;
    }

    float mrow[4], lrow[4], o[4][8];
#pragma unroll
    for (int i = 0; i < 4; i++) { mrow[i] = -INFINITY; lrow[i] = 0.f; }
#pragma unroll
    for (int i = 0; i < 4; i++)
#pragma unroll
        for (int j = 0; j < 8; j++) o[i][j] = 0.f;

    const int ntiles = q0 / FN + 1;
    for (int nt = 0; nt < ntiles; nt++) {
        const int n0 = nt * FN;
        __syncthreads();
#pragma unroll
        for (int i = 0; i < 8; i++) {
            int f  = t + i * 256;
            int m  = f >> 5;
            int dc = (f & 31) * 4;
            size_t gidx = ((size_t)((b * SEQ + n0 + m) * HEADS + h)) * FD + dc;
            float4 kv = *(const float4*)&k[gidx];
            Kt[(dc + 0) * FN + m] = kv.x;
            Kt[(dc + 1) * FN + m] = kv.y;
            Kt[(dc + 2) * FN + m] = kv.z;
            Kt[(dc + 3) * FN + m] = kv.w;
            float4 vv = *(const float4*)&v[gidx];
            *(float4*)&Vs[m * 132 + dc] = vv;
        }
        __syncthreads();

        float s[4][4];
#pragma unroll
        for (int i = 0; i < 4; i++)
#pragma unroll
            for (int j = 0; j < 4; j++) s[i][j] = 0.f;

#pragma unroll 4
        for (int d = 0; d < FD; d++) {
            float4 qa = *(const float4*)&Qt[d * FM + ty * 4];
            float4 ka = *(const float4*)&Kt[d * FN + tx * 4];
            float av[4] = {qa.x, qa.y, qa.z, qa.w};
            float bv[4] = {ka.x, ka.y, ka.z, ka.w};
#pragma unroll
            for (int i = 0; i < 4; i++)
#pragma unroll
                for (int j = 0; j < 4; j++)
                    s[i][j] += av[i] * bv[j];
        }

        if (n0 == q0) {
#pragma unroll
            for (int i = 0; i < 4; i++) {
                int row = ty * 4 + i;
#pragma unroll
                for (int j = 0; j < 4; j++) {
                    int col = tx * 4 + j;
                    if (col > row) s[i][j] = -INFINITY;
                }
            }
        }

#pragma unroll
        for (int i = 0; i < 4; i++) {
            float rm = fmaxf(fmaxf(s[i][0], s[i][1]), fmaxf(s[i][2], s[i][3]));
            rm = fmaxf(rm, __shfl_xor_sync(0xffffffffu, rm, 1));
            rm = fmaxf(rm, __shfl_xor_sync(0xffffffffu, rm, 2));
            rm = fmaxf(rm, __shfl_xor_sync(0xffffffffu, rm, 4));
            rm = fmaxf(rm, __shfl_xor_sync(0xffffffffu, rm, 8));
            float mnew = fmaxf(mrow[i], rm);
            float corr = __expf(mrow[i] - mnew);
            float rs = 0.f;
#pragma unroll
            for (int j = 0; j < 4; j++) {
                float p = __expf(s[i][j] - mnew);
                s[i][j] = p;
                rs += p;
            }
            rs += __shfl_xor_sync(0xffffffffu, rs, 1);
            rs += __shfl_xor_sync(0xffffffffu, rs, 2);
            rs += __shfl_xor_sync(0xffffffffu, rs, 4);
            rs += __shfl_xor_sync(0xffffffffu, rs, 8);
            lrow[i] = lrow[i] * corr + rs;
            mrow[i] = mnew;
#pragma unroll
            for (int j = 0; j < 8; j++) o[i][j] *= corr;
        }

#pragma unroll
        for (int i = 0; i < 4; i++)
#pragma unroll
            for (int j = 0; j < 4; j++)
                Pt[(tx * 4 + j) * 68 + ty * 4 + i] = s[i][j];
        __syncthreads();

#pragma unroll 4
        for (int kk = 0; kk < FN; kk++) {
            float4 pm = *(const float4*)&Pt[kk * 68 + ty * 4];
            float pv[4] = {pm.x, pm.y, pm.z, pm.w};
            float4 va = *(const float4*)&Vs[kk * 132 + tx * 8];
            float4 vb = *(const float4*)&Vs[kk * 132 + tx * 8 + 4];
            float vv[8] = {va.x, va.y, va.z, va.w, vb.x, vb.y, vb.z, vb.w};
#pragma unroll
            for (int i = 0; i < 4; i++)
#pragma unroll
                for (int j = 0; j < 8; j++)
                    o[i][j] += pv[i] * vv[j];
        }
    }

#pragma unroll
    for (int i = 0; i < 4; i++) {
        float inv = 1.0f / lrow[i];
        size_t row = (size_t)(b * SEQ + q0 + ty * 4 + i);
        float4 w0 = make_float4(o[i][0]*inv, o[i][1]*inv, o[i][2]*inv, o[i][3]*inv);
        float4 w1 = make_float4(o[i][4]*inv, o[i][5]*inv, o[i][6]*inv, o[i][7]*inv);
        *(float4*)&out[row * (HEADS * DHEAD) + h * DHEAD + tx * 8]     = w0;
        *(float4*)&out[row * (HEADS * DHEAD) + h * DHEAD + tx * 8 + 4] = w1;
    }
}

// ---------------------------------------------------------------------------
// Launcher
// ---------------------------------------------------------------------------
extern "C" void kernel_launch(void* const* d_in, const int* in_sizes, int n_in,
                              void* d_out, int out_size)
{
    (void)in_sizes; (void)n_in; (void)out_size;

    const float* h_in   = (const float*)d_in[0];
    const float* W_dkv  = (const float*)d_in[1];
    const float* b_dkv  = (const float*)d_in[2];
    const float* W_dq   = (const float*)d_in[3];
    const float* b_dq   = (const float*)d_in[4];
    const float* W_uk   = (const float*)d_in[5];
    const float* b_uk   = (const float*)d_in[6];
    const float* W_uv   = (const float*)d_in[7];
    const float* b_uv   = (const float*)d_in[8];
    const float* W_uq   = (const float*)d_in[9];
    const float* b_uq   = (const float*)d_in[10];
    const float* W_qr   = (const float*)d_in[11];
    const float* b_qr   = (const float*)d_in[12];
    const float* W_kr   = (const float*)d_in[13];
    const float* b_kr   = (const float*)d_in[14];
    const float* W_out  = (const float*)d_in[15];
    const float* b_out  = (const float*)d_in[16];

    float* out_main = (float*)d_out;
    float* out_ckv  = out_main + (size_t)NTOK * EMB;
    float* out_krot = out_ckv + (size_t)NTOK * CLAT;

    float *p_cq, *p_qr, *p_kr, *p_q, *p_k, *p_v, *p_ao;
    cudaGetSymbolAddress((void**)&p_cq, g_cq);
    cudaGetSymbolAddress((void**)&p_qr, g_qr);
    cudaGetSymbolAddress((void**)&p_kr, g_kr);
    cudaGetSymbolAddress((void**)&p_q,  g_q);
    cudaGetSymbolAddress((void**)&p_k,  g_k);
    cudaGetSymbolAddress((void**)&p_v,  g_v);
    cudaGetSymbolAddress((void**)&p_ao, g_ao);

    cudaFuncSetAttribute(mma_gemm_kernel, cudaFuncAttributeMaxDynamicSharedMemorySize, GSMEM);

    dim3 thr(256);
    const int M = NTOK;

    // 1. c_kv = h @ W_dkv  -> output region
    mma_gemm_kernel<<<dim3(CLAT/BN, M/BM), thr, GSMEM>>>(h_in, W_dkv, b_dkv, out_ckv,
        M, CLAT, EMB, CLAT, CLAT, 0, CLAT);
    // 2. c_q = h @ W_dq
    mma_gemm_kernel<<<dim3(CLAT/BN, M/BM), thr, GSMEM>>>(h_in, W_dq, b_dq, p_cq,
        M, CLAT, EMB, CLAT, CLAT, 0, CLAT);
    // 3. k_rot_pre = h @ W_kr
    mma_gemm_kernel<<<dim3((HEADS*DROPE)/BN, M/BM), thr, GSMEM>>>(h_in, W_kr, b_kr, p_kr,
        M, HEADS*DROPE, EMB, HEADS*DROPE, HEADS*DROPE, 0, HEADS*DROPE);
    // 4. k_base = c_kv @ W_uk -> assembled K (cols h*128 + 0..95)
    mma_gemm_kernel<<<dim3((HEADS*SPLIT)/BN, M/BM), thr, GSMEM>>>(out_ckv, W_uk, b_uk, p_k,
        M, HEADS*SPLIT, CLAT, SPLIT, DHEAD, 0, HEADS*DHEAD);
    // 5. v = c_kv @ W_uv
    mma_gemm_kernel<<<dim3((HEADS*DHEAD)/BN, M/BM), thr, GSMEM>>>(out_ckv, W_uv, b_uv, p_v,
        M, HEADS*DHEAD, CLAT, HEADS*DHEAD, HEADS*DHEAD, 0, HEADS*DHEAD);
    // 6. q_base = c_q @ W_uq -> assembled Q
    mma_gemm_kernel<<<dim3((HEADS*SPLIT)/BN, M/BM), thr, GSMEM>>>(p_cq, W_uq, b_uq, p_q,
        M, HEADS*SPLIT, CLAT, SPLIT, DHEAD, 0, HEADS*DHEAD);
    // 7. q_rot_pre = c_q @ W_qr
    mma_gemm_kernel<<<dim3((HEADS*DROPE)/BN, M/BM), thr, GSMEM>>>(p_cq, W_qr, b_qr, p_qr,
        M, HEADS*DROPE, CLAT, HEADS*DROPE, HEADS*DROPE, 0, HEADS*DROPE);
    // 8. rotary
    rotary_kernel<<<(NTOK*HEADS + 255)/256, 256>>>(p_qr, p_kr, p_q, p_k, out_krot);
    // 9. attention
    {
        size_t smem_bytes = (size_t)SMEM_FLOATS * sizeof(float);
        cudaFuncSetAttribute(attn_kernel, cudaFuncAttributeMaxDynamicSharedMemorySize,
                             (int)smem_bytes);
        attn_kernel<<<dim3(SEQ/FM, BATCH*HEADS), thr, smem_bytes>>>(p_q, p_k, p_v, p_ao);
    }
    // 10. out = attn_out @ W_out + b_out
    mma_gemm_kernel<<<dim3(EMB/BN, M/BM), thr, GSMEM>>>(p_ao, W_out, b_out, out_main,
        M, EMB, HEADS*DHEAD, EMB, EMB, 0, EMB);
}

// round 4
// speedup vs baseline: 2.9927x; 2.0843x over previous
#include <cuda_runtime.h>
#include <cuda_bf16.h>
#include <math.h>
#include <cstdint>

// Problem constants
#define BATCH 2
#define SEQ   2048
#define EMB   2048
#define HEADS 16
#define DHEAD 128
#define DROPE 32
#define SPLIT 96
#define CLAT  512
#define NTOK  (BATCH*SEQ)          // 4096

// ---------------------------------------------------------------------------
// Scratch buffers (device globals; no allocation allowed)
// ---------------------------------------------------------------------------
__device__ float g_cq[NTOK * CLAT];
__device__ float g_qr[NTOK * HEADS * DROPE];
__device__ float g_kr[NTOK * HEADS * DROPE];
__device__ float g_q [NTOK * HEADS * DHEAD];
__device__ float g_k [NTOK * HEADS * DHEAD];
__device__ float g_v [NTOK * HEADS * DHEAD];
__device__ float g_ao[NTOK * HEADS * DHEAD];

// ---------------------------------------------------------------------------
// Helpers
// ---------------------------------------------------------------------------
__device__ __forceinline__ uint32_t smem_u32(const void* p) {
    uint32_t a;
    asm("{ .reg .u64 t; cvta.to.shared.u64 t, %1; cvt.u32.u64 %0, t; }"
        : "=r"(a) : "l"(p));
    return a;
}

// pack two floats to bf16x2: first arg -> low half, second -> high half
__device__ __forceinline__ uint32_t packbf(float lo_elem, float hi_elem) {
    uint32_t r;
    asm("cvt.rn.bf16x2.f32 %0, %1, %2;" : "=r"(r) : "f"(hi_elem), "f"(lo_elem));
    return r;
}
__device__ __forceinline__ float bf16rt(float x) {   // round-trip through bf16
    __nv_bfloat16 h = __float2bfloat16(x);
    return __bfloat162float(h);
}

__device__ __forceinline__ void ldsm_x4(uint32_t& r0, uint32_t& r1, uint32_t& r2,
                                        uint32_t& r3, uint32_t addr) {
    asm volatile("ldmatrix.sync.aligned.m8n8.x4.shared.b16 {%0,%1,%2,%3}, [%4];"
                 : "=r"(r0), "=r"(r1), "=r"(r2), "=r"(r3) : "r"(addr));
}
__device__ __forceinline__ void ldsm_x4t(uint32_t& r0, uint32_t& r1, uint32_t& r2,
                                         uint32_t& r3, uint32_t addr) {
    asm volatile("ldmatrix.sync.aligned.m8n8.x4.trans.shared.b16 {%0,%1,%2,%3}, [%4];"
                 : "=r"(r0), "=r"(r1), "=r"(r2), "=r"(r3) : "r"(addr));
}

__device__ __forceinline__ void mma_bf16(float* d, const uint32_t* a, const uint32_t* b) {
    asm volatile(
        "mma.sync.aligned.m16n8k16.row.col.f32.bf16.bf16.f32 "
        "{%0,%1,%2,%3}, {%4,%5,%6,%7}, {%8,%9}, {%0,%1,%2,%3};"
        : "+f"(d[0]), "+f"(d[1]), "+f"(d[2]), "+f"(d[3])
        : "r"(a[0]), "r"(a[1]), "r"(a[2]), "r"(a[3]), "r"(b[0]), "r"(b[1]));
}

// ---------------------------------------------------------------------------
// 3xBF16 mma.sync GEMM + bias (unchanged from round 3)
// ---------------------------------------------------------------------------
#define BM 128
#define BN 128
#define BK 32
#define PA 40
#define PB 136
#define A_PLANE 10240
#define B_PLANE 8704
#define OFF_AHI 0
#define OFF_ALO (A_PLANE)
#define OFF_BHI (2*A_PLANE)
#define OFF_BLO (2*A_PLANE + B_PLANE)
#define SBUF    (2*A_PLANE + 2*B_PLANE)
#define GSMEM   (2*SBUF)

__global__ __launch_bounds__(256, 1)
void mma_gemm_kernel(const float* __restrict__ A, const float* __restrict__ B,
                     const float* __restrict__ bias, float* __restrict__ C,
                     int M, int N, int K,
                     int seg, int hstride, int col_off, int ostride)
{
    extern __shared__ char smc[];
    const uint32_t sb = smem_u32(smc);
    const int t    = threadIdx.x;
    const int lane = t & 31;
    const int w    = t >> 5;
    const int m0   = blockIdx.y * BM;
    const int n0   = blockIdx.x * BN;
    const int wm   = (w >> 2) * 64;
    const int wn   = (w & 3) * 32;

    float acc[4][4][4];
#pragma unroll
    for (int i = 0; i < 4; i++)
#pragma unroll
        for (int j = 0; j < 4; j++)
#pragma unroll
            for (int r = 0; r < 4; r++) acc[i][j][r] = 0.f;

    const uint32_t aLane = (uint32_t)((wm + (lane & 15)) * PA + (lane >> 4) * 8) * 2;
    const uint32_t bLaneRow = (uint32_t)(lane & 15) * PB * 2;
    const uint32_t bLaneCol = (uint32_t)(wn + (lane >> 4) * 8) * 2;

    const int NC = K / BK;
    float4 pa[4], pb[4];

    {
        const int kk = 0;
#pragma unroll
        for (int i = 0; i < 4; i++) {
            int f = t + i * 256;
            pa[i] = *(const float4*)&A[(size_t)(m0 + (f >> 3)) * K + kk + (f & 7) * 4];
        }
#pragma unroll
        for (int i = 0; i < 4; i++) {
            int f = t + i * 256;
            pb[i] = *(const float4*)&B[(size_t)(kk + (f >> 5)) * N + n0 + (f & 31) * 4];
        }
        char* buf = smc;
#pragma unroll
        for (int i = 0; i < 4; i++) {
            int f = t + i * 256;
            uint32_t off = (uint32_t)((f >> 3) * PA + (f & 7) * 4) * 2;
            float h0 = bf16rt(pa[i].x), h1 = bf16rt(pa[i].y);
            float h2 = bf16rt(pa[i].z), h3 = bf16rt(pa[i].w);
            *(uint32_t*)(buf + OFF_AHI + off)     = packbf(h0, h1);
            *(uint32_t*)(buf + OFF_AHI + off + 4) = packbf(h2, h3);
            *(uint32_t*)(buf + OFF_ALO + off)     = packbf(pa[i].x - h0, pa[i].y - h1);
            *(uint32_t*)(buf + OFF_ALO + off + 4) = packbf(pa[i].z - h2, pa[i].w - h3);
        }
#pragma unroll
        for (int i = 0; i < 4; i++) {
            int f = t + i * 256;
            uint32_t off = (uint32_t)((f >> 5) * PB + (f & 31) * 4) * 2;
            float h0 = bf16rt(pb[i].x), h1 = bf16rt(pb[i].y);
            float h2 = bf16rt(pb[i].z), h3 = bf16rt(pb[i].w);
            *(uint32_t*)(buf + OFF_BHI + off)     = packbf(h0, h1);
            *(uint32_t*)(buf + OFF_BHI + off + 4) = packbf(h2, h3);
            *(uint32_t*)(buf + OFF_BLO + off)     = packbf(pb[i].x - h0, pb[i].y - h1);
            *(uint32_t*)(buf + OFF_BLO + off + 4) = packbf(pb[i].z - h2, pb[i].w - h3);
        }
    }
    __syncthreads();

    for (int ch = 0; ch < NC; ch++) {
        const int p = ch & 1;
        const uint32_t base = sb + (uint32_t)p * SBUF;

        if (ch + 1 < NC) {
            const int kk = (ch + 1) * BK;
#pragma unroll
            for (int i = 0; i < 4; i++) {
                int f = t + i * 256;
                pa[i] = *(const float4*)&A[(size_t)(m0 + (f >> 3)) * K + kk + (f & 7) * 4];
            }
#pragma unroll
            for (int i = 0; i < 4; i++) {
                int f = t + i * 256;
                pb[i] = *(const float4*)&B[(size_t)(kk + (f >> 5)) * N + n0 + (f & 31) * 4];
            }
        }

#pragma unroll
        for (int ks = 0; ks < 2; ks++) {
            uint32_t Ah[4][4], Al[4][4], Bh[2][4], Bl[2][4];
            const uint32_t aOff = aLane + (uint32_t)ks * 32;
            const uint32_t bOff = bLaneRow + (uint32_t)ks * (16 * PB * 2);
#pragma unroll
            for (int mt = 0; mt < 4; mt++) {
                uint32_t ad = base + aOff + (uint32_t)mt * (16 * PA * 2);
                ldsm_x4(Ah[mt][0], Ah[mt][1], Ah[mt][2], Ah[mt][3], ad + OFF_AHI);
                ldsm_x4(Al[mt][0], Al[mt][1], Al[mt][2], Al[mt][3], ad + OFF_ALO);
            }
#pragma unroll
            for (int np = 0; np < 2; np++) {
                uint32_t bd = base + bOff + bLaneCol + (uint32_t)np * 32;
                ldsm_x4t(Bh[np][0], Bh[np][1], Bh[np][2], Bh[np][3], bd + OFF_BHI);
                ldsm_x4t(Bl[np][0], Bl[np][1], Bl[np][2], Bl[np][3], bd + OFF_BLO);
            }
#pragma unroll
            for (int mt = 0; mt < 4; mt++) {
#pragma unroll
                for (int nt = 0; nt < 4; nt++) {
                    const uint32_t* bh = &Bh[nt >> 1][(nt & 1) * 2];
                    const uint32_t* bl = &Bl[nt >> 1][(nt & 1) * 2];
                    mma_bf16(acc[mt][nt], Ah[mt], bh);
                    mma_bf16(acc[mt][nt], Ah[mt], bl);
                    mma_bf16(acc[mt][nt], Al[mt], bh);
                }
            }
        }

        if (ch + 1 < NC) {
            char* buf = smc + (p ^ 1) * SBUF;
#pragma unroll
            for (int i = 0; i < 4; i++) {
                int f = t + i * 256;
                uint32_t off = (uint32_t)((f >> 3) * PA + (f & 7) * 4) * 2;
                float h0 = bf16rt(pa[i].x), h1 = bf16rt(pa[i].y);
                float h2 = bf16rt(pa[i].z), h3 = bf16rt(pa[i].w);
                *(uint32_t*)(buf + OFF_AHI + off)     = packbf(h0, h1);
                *(uint32_t*)(buf + OFF_AHI + off + 4) = packbf(h2, h3);
                *(uint32_t*)(buf + OFF_ALO + off)     = packbf(pa[i].x - h0, pa[i].y - h1);
                *(uint32_t*)(buf + OFF_ALO + off + 4) = packbf(pa[i].z - h2, pa[i].w - h3);
            }
#pragma unroll
            for (int i = 0; i < 4; i++) {
                int f = t + i * 256;
                uint32_t off = (uint32_t)((f >> 5) * PB + (f & 31) * 4) * 2;
                float h0 = bf16rt(pb[i].x), h1 = bf16rt(pb[i].y);
                float h2 = bf16rt(pb[i].z), h3 = bf16rt(pb[i].w);
                *(uint32_t*)(buf + OFF_BHI + off)     = packbf(h0, h1);
                *(uint32_t*)(buf + OFF_BHI + off + 4) = packbf(h2, h3);
                *(uint32_t*)(buf + OFF_BLO + off)     = packbf(pb[i].x - h0, pb[i].y - h1);
                *(uint32_t*)(buf + OFF_BLO + off + 4) = packbf(pb[i].z - h2, pb[i].w - h3);
            }
        }
        __syncthreads();
    }

    const int r0 = lane >> 2;
    const int c0 = (lane & 3) * 2;
#pragma unroll
    for (int mt = 0; mt < 4; mt++) {
#pragma unroll
        for (int nt = 0; nt < 4; nt++) {
            int n = n0 + wn + nt * 8 + c0;
            int oc = (n / seg) * hstride + (n % seg) + col_off;
            float b0 = bias[n], b1 = bias[n + 1];
            int mrow0 = m0 + wm + mt * 16 + r0;
            float2 v0 = make_float2(acc[mt][nt][0] + b0, acc[mt][nt][1] + b1);
            *(float2*)&C[(size_t)mrow0 * ostride + oc] = v0;
            float2 v1 = make_float2(acc[mt][nt][2] + b0, acc[mt][nt][3] + b1);
            *(float2*)&C[(size_t)(mrow0 + 8) * ostride + oc] = v1;
        }
    }
}

// ---------------------------------------------------------------------------
// Rotary kernel (unchanged)
// ---------------------------------------------------------------------------
__global__ void rotary_kernel(const float* __restrict__ qr,
                              const float* __restrict__ kr,
                              float* __restrict__ qout,
                              float* __restrict__ kout,
                              float* __restrict__ krot_out)
{
    int idx = blockIdx.x * blockDim.x + threadIdx.x;
    if (idx >= NTOK * HEADS) return;
    int h   = idx & (HEADS - 1);
    int tok = idx >> 4;
    int s   = tok & (SEQ - 1);
    float tpos = (float)s / 40.0f;

    float xq[32], xk[32];
#pragma unroll
    for (int i = 0; i < 8; i++) {
        float4 a = *(const float4*)&qr[(size_t)idx * 32 + i * 4];
        xq[i*4+0]=a.x; xq[i*4+1]=a.y; xq[i*4+2]=a.z; xq[i*4+3]=a.w;
        float4 b = *(const float4*)&kr[(size_t)idx * 32 + i * 4];
        xk[i*4+0]=b.x; xk[i*4+1]=b.y; xk[i*4+2]=b.z; xk[i*4+3]=b.w;
    }

    float yq[32], yk[32];
#pragma unroll
    for (int j = 0; j < 8; j++) {
        float invf = exp2f(-1.6609640474436813f * (float)j);
        float ang = tpos * invf;
        float sj, cj;
        sincosf(ang, &sj, &cj);
        yq[j]     = xq[j] * cj - xq[j + 8] * sj;
        yq[j + 8] = xq[j + 8] * cj + xq[j] * sj;
        yk[j]     = xk[j] * cj - xk[j + 8] * sj;
        yk[j + 8] = xk[j + 8] * cj + xk[j] * sj;
    }
#pragma unroll
    for (int d = 16; d < 32; d++) { yq[d] = xq[d]; yk[d] = xk[d]; }

    size_t obase = (size_t)tok * (HEADS * DHEAD) + h * DHEAD + SPLIT;
#pragma unroll
    for (int i = 0; i < 8; i++) {
        float4 a = make_float4(yq[i*4], yq[i*4+1], yq[i*4+2], yq[i*4+3]);
        *(float4*)&qout[obase + i * 4] = a;
        float4 b = make_float4(yk[i*4], yk[i*4+1], yk[i*4+2], yk[i*4+3]);
        *(float4*)&kout[obase + i * 4] = b;
        *(float4*)&krot_out[(size_t)idx * 32 + i * 4] = b;
    }
}

// ---------------------------------------------------------------------------
// Causal flash-attention with 3xBF16 mma.sync.
// CTA: 128 q-rows, one (b,h). 8 warps, each owns m16 q-slab. kt tiles of 64.
// ---------------------------------------------------------------------------
#define AM 128
#define AN 64
#define AD 128
#define APH 136                          // smem pitch in halves
#define AQHI 0
#define AQLO (AM*APH*2)                  // 34816
#define AKHI (2*AM*APH*2)                // 69632
#define AKLO (AKHI + AN*APH*2)
#define AVHI (AKLO + AN*APH*2)
#define AVLO (AVHI + AN*APH*2)
#define ASMEM (AVLO + AN*APH*2)          // 139264 bytes

__global__ __launch_bounds__(256, 1)
void attn_mma_kernel(const float* __restrict__ q, const float* __restrict__ k,
                     const float* __restrict__ v, float* __restrict__ out)
{
    extern __shared__ char smc[];
    const uint32_t sb = smem_u32(smc);
    const int t    = threadIdx.x;
    const int lane = t & 31;
    const int w    = t >> 5;
    const int bh   = blockIdx.y;
    const int b    = bh >> 4;
    const int h    = bh & 15;
    const int q0   = blockIdx.x * AM;
    const float scale = 0.08838834764831845f;   // 1/sqrt(128)

    // ---- load Q (scaled, split hi/lo) ----
#pragma unroll
    for (int i = 0; i < 16; i++) {
        int f = t + i * 256;                    // 0..4095 float4s
        int row = f >> 5;
        int dc  = (f & 31) * 4;
        float4 qv = *(const float4*)&q[((size_t)((b * SEQ + q0 + row) * HEADS + h)) * AD + dc];
        qv.x *= scale; qv.y *= scale; qv.z *= scale; qv.w *= scale;
        float h0 = bf16rt(qv.x), h1 = bf16rt(qv.y), h2 = bf16rt(qv.z), h3 = bf16rt(qv.w);
        uint32_t off = (uint32_t)(row * APH + dc) * 2;
        *(uint32_t*)(smc + AQHI + off)     = packbf(h0, h1);
        *(uint32_t*)(smc + AQHI + off + 4) = packbf(h2, h3);
        *(uint32_t*)(smc + AQLO + off)     = packbf(qv.x - h0, qv.y - h1);
        *(uint32_t*)(smc + AQLO + off + 4) = packbf(qv.z - h2, qv.w - h3);
    }

    float mrow[2] = {-INFINITY, -INFINITY};
    float lrow[2] = {0.f, 0.f};
    float O[16][4];
#pragma unroll
    for (int i = 0; i < 16; i++)
#pragma unroll
        for (int r = 0; r < 4; r++) O[i][r] = 0.f;

    const int ntiles = q0 / AN + 2;
    for (int nt = 0; nt < ntiles; nt++) {
        const int n0 = nt * AN;
        __syncthreads();
        // ---- load K,V tile (split) ----
#pragma unroll
        for (int i = 0; i < 8; i++) {
            int f = t + i * 256;
            int row = f >> 5;
            int dc  = (f & 31) * 4;
            size_t gidx = ((size_t)((b * SEQ + n0 + row) * HEADS + h)) * AD + dc;
            uint32_t off = (uint32_t)(row * APH + dc) * 2;
            float4 kv = *(const float4*)&k[gidx];
            float h0 = bf16rt(kv.x), h1 = bf16rt(kv.y), h2 = bf16rt(kv.z), h3 = bf16rt(kv.w);
            *(uint32_t*)(smc + AKHI + off)     = packbf(h0, h1);
            *(uint32_t*)(smc + AKHI + off + 4) = packbf(h2, h3);
            *(uint32_t*)(smc + AKLO + off)     = packbf(kv.x - h0, kv.y - h1);
            *(uint32_t*)(smc + AKLO + off + 4) = packbf(kv.z - h2, kv.w - h3);
            float4 vv = *(const float4*)&v[gidx];
            h0 = bf16rt(vv.x); h1 = bf16rt(vv.y); h2 = bf16rt(vv.z); h3 = bf16rt(vv.w);
            *(uint32_t*)(smc + AVHI + off)     = packbf(h0, h1);
            *(uint32_t*)(smc + AVHI + off + 4) = packbf(h2, h3);
            *(uint32_t*)(smc + AVLO + off)     = packbf(vv.x - h0, vv.y - h1);
            *(uint32_t*)(smc + AVLO + off + 4) = packbf(vv.z - h2, vv.w - h3);
        }
        __syncthreads();

        const bool active = (q0 + w * 16 + 15) >= n0;
        if (!active) continue;

        // ---- S = Q K^T ----
        float S[8][4];
#pragma unroll
        for (int nf = 0; nf < 8; nf++)
#pragma unroll
            for (int r = 0; r < 4; r++) S[nf][r] = 0.f;

#pragma unroll
        for (int ks = 0; ks < 8; ks++) {
            uint32_t ah[4], al[4];
            uint32_t ad = sb + (uint32_t)((w * 16 + (lane & 15)) * APH + ks * 16 + (lane >> 4) * 8) * 2;
            ldsm_x4(ah[0], ah[1], ah[2], ah[3], ad + AQHI);
            ldsm_x4(al[0], al[1], al[2], al[3], ad + AQLO);
#pragma unroll
            for (int g = 0; g < 4; g++) {
                // b-frags from K[kt][d]: rows = n (kt), cols = k (d); non-trans
                uint32_t bd = sb + (uint32_t)((g * 16 + (lane & 7) + (lane >> 4) * 8) * APH
                                              + ks * 16 + ((lane >> 3) & 1) * 8) * 2;
                uint32_t kh[4], kl[4];
                ldsm_x4(kh[0], kh[1], kh[2], kh[3], bd + AKHI);
                ldsm_x4(kl[0], kl[1], kl[2], kl[3], bd + AKLO);
                mma_bf16(S[2*g],   ah, &kh[0]);
                mma_bf16(S[2*g],   ah, &kl[0]);
                mma_bf16(S[2*g],   al, &kh[0]);
                mma_bf16(S[2*g+1], ah, &kh[2]);
                mma_bf16(S[2*g+1], ah, &kl[2]);
                mma_bf16(S[2*g+1], al, &kh[2]);
            }
        }

        // ---- causal mask (boundary tiles only) ----
        if (n0 + AN - 1 > q0 + w * 16) {
            int grow0 = q0 + w * 16 + (lane >> 2);
#pragma unroll
            for (int nf = 0; nf < 8; nf++) {
                int col = n0 + nf * 8 + (lane & 3) * 2;
#pragma unroll
                for (int r = 0; r < 4; r++) {
                    int gr = grow0 + (r >> 1) * 8;
                    int gc = col + (r & 1);
                    if (gc > gr) S[nf][r] = -INFINITY;
                }
            }
        }

        // ---- online softmax ----
        float corr[2];
#pragma unroll
        for (int rr = 0; rr < 2; rr++) {
            float rm = -INFINITY;
#pragma unroll
            for (int nf = 0; nf < 8; nf++)
                rm = fmaxf(rm, fmaxf(S[nf][rr*2], S[nf][rr*2+1]));
            rm = fmaxf(rm, __shfl_xor_sync(0xffffffffu, rm, 1));
            rm = fmaxf(rm, __shfl_xor_sync(0xffffffffu, rm, 2));
            float mnew = fmaxf(mrow[rr], rm);
            corr[rr] = __expf(mrow[rr] - mnew);
            float rs = 0.f;
#pragma unroll
            for (int nf = 0; nf < 8; nf++) {
                float p0 = __expf(S[nf][rr*2]   - mnew);
                float p1 = __expf(S[nf][rr*2+1] - mnew);
                S[nf][rr*2]   = p0;
                S[nf][rr*2+1] = p1;
                rs += p0 + p1;
            }
            rs += __shfl_xor_sync(0xffffffffu, rs, 1);
            rs += __shfl_xor_sync(0xffffffffu, rs, 2);
            lrow[rr] = lrow[rr] * corr[rr] + rs;
            mrow[rr] = mnew;
        }
#pragma unroll
        for (int i = 0; i < 16; i++) {
            O[i][0] *= corr[0]; O[i][1] *= corr[0];
            O[i][2] *= corr[1]; O[i][3] *= corr[1];
        }

        // ---- O += P V ----
#pragma unroll
        for (int j = 0; j < 4; j++) {
            // P a-frags (m16k16) from S[2j], S[2j+1], split hi/lo
            uint32_t ph[4], pl[4];
            {
                float s00 = S[2*j][0],   s01 = S[2*j][1],   s02 = S[2*j][2],   s03 = S[2*j][3];
                float s10 = S[2*j+1][0], s11 = S[2*j+1][1], s12 = S[2*j+1][2], s13 = S[2*j+1][3];
                float h00 = bf16rt(s00), h01 = bf16rt(s01), h02 = bf16rt(s02), h03 = bf16rt(s03);
                float h10 = bf16rt(s10), h11 = bf16rt(s11), h12 = bf16rt(s12), h13 = bf16rt(s13);
                ph[0] = packbf(h00, h01); ph[1] = packbf(h02, h03);
                ph[2] = packbf(h10, h11); ph[3] = packbf(h12, h13);
                pl[0] = packbf(s00 - h00, s01 - h01); pl[1] = packbf(s02 - h02, s03 - h03);
                pl[2] = packbf(s10 - h10, s11 - h11); pl[3] = packbf(s12 - h12, s13 - h13);
            }
#pragma unroll
            for (int g = 0; g < 8; g++) {
                uint32_t vd = sb + (uint32_t)((j * 16 + (lane & 15)) * APH
                                              + g * 16 + (lane >> 4) * 8) * 2;
                uint32_t vh[4], vl[4];
                ldsm_x4t(vh[0], vh[1], vh[2], vh[3], vd + AVHI);
                ldsm_x4t(vl[0], vl[1], vl[2], vl[3], vd + AVLO);
                mma_bf16(O[2*g],   ph, &vh[0]);
                mma_bf16(O[2*g],   ph, &vl[0]);
                mma_bf16(O[2*g],   pl, &vh[0]);
                mma_bf16(O[2*g+1], ph, &vh[2]);
                mma_bf16(O[2*g+1], ph, &vl[2]);
                mma_bf16(O[2*g+1], pl, &vh[2]);
            }
        }
    }

    // ---- epilogue ----
    float inv0 = 1.0f / lrow[0];
    float inv1 = 1.0f / lrow[1];
#pragma unroll
    for (int nd = 0; nd < 16; nd++) {
        int d = nd * 8 + (lane & 3) * 2;
        size_t row0 = (size_t)(b * SEQ + q0 + w * 16 + (lane >> 2));
        *(float2*)&out[row0 * (HEADS * DHEAD) + h * DHEAD + d] =
            make_float2(O[nd][0] * inv0, O[nd][1] * inv0);
        *(float2*)&out[(row0 + 8) * (HEADS * DHEAD) + h * DHEAD + d] =
            make_float2(O[nd][2] * inv1, O[nd][3] * inv1);
    }
}

// ---------------------------------------------------------------------------
// Launcher
// ---------------------------------------------------------------------------
extern "C" void kernel_launch(void* const* d_in, const int* in_sizes, int n_in,
                              void* d_out, int out_size)
{
    (void)in_sizes; (void)n_in; (void)out_size;

    const float* h_in   = (const float*)d_in[0];
    const float* W_dkv  = (const float*)d_in[1];
    const float* b_dkv  = (const float*)d_in[2];
    const float* W_dq   = (const float*)d_in[3];
    const float* b_dq   = (const float*)d_in[4];
    const float* W_uk   = (const float*)d_in[5];
    const float* b_uk   = (const float*)d_in[6];
    const float* W_uv   = (const float*)d_in[7];
    const float* b_uv   = (const float*)d_in[8];
    const float* W_uq   = (const float*)d_in[9];
    const float* b_uq   = (const float*)d_in[10];
    const float* W_qr   = (const float*)d_in[11];
    const float* b_qr   = (const float*)d_in[12];
    const float* W_kr   = (const float*)d_in[13];
    const float* b_kr   = (const float*)d_in[14];
    const float* W_out  = (const float*)d_in[15];
    const float* b_out  = (const float*)d_in[16];

    float* out_main = (float*)d_out;
    float* out_ckv  = out_main + (size_t)NTOK * EMB;
    float* out_krot = out_ckv + (size_t)NTOK * CLAT;

    float *p_cq, *p_qr, *p_kr, *p_q, *p_k, *p_v, *p_ao;
    cudaGetSymbolAddress((void**)&p_cq, g_cq);
    cudaGetSymbolAddress((void**)&p_qr, g_qr);
    cudaGetSymbolAddress((void**)&p_kr, g_kr);
    cudaGetSymbolAddress((void**)&p_q,  g_q);
    cudaGetSymbolAddress((void**)&p_k,  g_k);
    cudaGetSymbolAddress((void**)&p_v,  g_v);
    cudaGetSymbolAddress((void**)&p_ao, g_ao);

    cudaFuncSetAttribute(mma_gemm_kernel, cudaFuncAttributeMaxDynamicSharedMemorySize, GSMEM);
    cudaFuncSetAttribute(attn_mma_kernel, cudaFuncAttributeMaxDynamicSharedMemorySize, ASMEM);

    dim3 thr(256);
    const int M = NTOK;

    // 1. c_kv = h @ W_dkv  -> output region
    mma_gemm_kernel<<<dim3(CLAT/BN, M/BM), thr, GSMEM>>>(h_in, W_dkv, b_dkv, out_ckv,
        M, CLAT, EMB, CLAT, CLAT, 0, CLAT);
    // 2. c_q = h @ W_dq
    mma_gemm_kernel<<<dim3(CLAT/BN, M/BM), thr, GSMEM>>>(h_in, W_dq, b_dq, p_cq,
        M, CLAT, EMB, CLAT, CLAT, 0, CLAT);
    // 3. k_rot_pre = h @ W_kr
    mma_gemm_kernel<<<dim3((HEADS*DROPE)/BN, M/BM), thr, GSMEM>>>(h_in, W_kr, b_kr, p_kr,
        M, HEADS*DROPE, EMB, HEADS*DROPE, HEADS*DROPE, 0, HEADS*DROPE);
    // 4. k_base = c_kv @ W_uk -> assembled K
    mma_gemm_kernel<<<dim3((HEADS*SPLIT)/BN, M/BM), thr, GSMEM>>>(out_ckv, W_uk, b_uk, p_k,
        M, HEADS*SPLIT, CLAT, SPLIT, DHEAD, 0, HEADS*DHEAD);
    // 5. v = c_kv @ W_uv
    mma_gemm_kernel<<<dim3((HEADS*DHEAD)/BN, M/BM), thr, GSMEM>>>(out_ckv, W_uv, b_uv, p_v,
        M, HEADS*DHEAD, CLAT, HEADS*DHEAD, HEADS*DHEAD, 0, HEADS*DHEAD);
    // 6. q_base = c_q @ W_uq -> assembled Q
    mma_gemm_kernel<<<dim3((HEADS*SPLIT)/BN, M/BM), thr, GSMEM>>>(p_cq, W_uq, b_uq, p_q,
        M, HEADS*SPLIT, CLAT, SPLIT, DHEAD, 0, HEADS*DHEAD);
    // 7. q_rot_pre = c_q @ W_qr
    mma_gemm_kernel<<<dim3((HEADS*DROPE)/BN, M/BM), thr, GSMEM>>>(p_cq, W_qr, b_qr, p_qr,
        M, HEADS*DROPE, CLAT, HEADS*DROPE, HEADS*DROPE, 0, HEADS*DROPE);
    // 8. rotary
    rotary_kernel<<<(NTOK*HEADS + 255)/256, 256>>>(p_qr, p_kr, p_q, p_k, out_krot);
    // 9. attention (3xBF16 mma)
    attn_mma_kernel<<<dim3(SEQ/AM, BATCH*HEADS), thr, ASMEM>>>(p_q, p_k, p_v, p_ao);
    // 10. out = attn_out @ W_out + b_out
    mma_gemm_kernel<<<dim3(EMB/BN, M/BM), thr, GSMEM>>>(p_ao, W_out, b_out, out_main,
        M, EMB, HEADS*DHEAD, EMB, EMB, 0, EMB);
}

// round 5
// speedup vs baseline: 3.1131x; 1.0402x over previous
#include <cuda_runtime.h>
#include <cuda_bf16.h>
#include <math.h>
#include <cstdint>

// Problem constants
#define BATCH 2
#define SEQ   2048
#define EMB   2048
#define HEADS 16
#define DHEAD 128
#define DROPE 32
#define SPLIT 96
#define CLAT  512
#define NTOK  (BATCH*SEQ)          // 4096
#define HD    (HEADS*DHEAD)        // 2048

// ---------------------------------------------------------------------------
// Global scratch (device globals; no allocation allowed)
// ---------------------------------------------------------------------------
// bf16 plane pool: sequential offsets (elems)
constexpr size_t OF_HH   = 0;
constexpr size_t OF_HL   = OF_HH   + (size_t)NTOK*EMB;
constexpr size_t OF_DKVH = OF_HL   + (size_t)NTOK*EMB;
constexpr size_t OF_DKVL = OF_DKVH + (size_t)EMB*CLAT;
constexpr size_t OF_DQH  = OF_DKVL + (size_t)EMB*CLAT;
constexpr size_t OF_DQL  = OF_DQH  + (size_t)EMB*CLAT;
constexpr size_t OF_KRH  = OF_DQL  + (size_t)EMB*CLAT;
constexpr size_t OF_KRL  = OF_KRH  + (size_t)EMB*(HEADS*DROPE);
constexpr size_t OF_UKH  = OF_KRL  + (size_t)EMB*(HEADS*DROPE);
constexpr size_t OF_UKL  = OF_UKH  + (size_t)CLAT*(HEADS*SPLIT);
constexpr size_t OF_UVH  = OF_UKL  + (size_t)CLAT*(HEADS*SPLIT);
constexpr size_t OF_UVL  = OF_UVH  + (size_t)CLAT*HD;
constexpr size_t OF_UQH  = OF_UVL  + (size_t)CLAT*HD;
constexpr size_t OF_UQL  = OF_UQH  + (size_t)CLAT*(HEADS*SPLIT);
constexpr size_t OF_QRH  = OF_UQL  + (size_t)CLAT*(HEADS*SPLIT);
constexpr size_t OF_QRL  = OF_QRH  + (size_t)CLAT*(HEADS*DROPE);
constexpr size_t OF_OUTH = OF_QRL  + (size_t)CLAT*(HEADS*DROPE);
constexpr size_t OF_OUTL = OF_OUTH + (size_t)HD*EMB;
constexpr size_t OF_CKVH = OF_OUTL + (size_t)HD*EMB;
constexpr size_t OF_CKVL = OF_CKVH + (size_t)NTOK*CLAT;
constexpr size_t OF_CQH  = OF_CKVL + (size_t)NTOK*CLAT;
constexpr size_t OF_CQL  = OF_CQH  + (size_t)NTOK*CLAT;
constexpr size_t OF_QH   = OF_CQL  + (size_t)NTOK*CLAT;
constexpr size_t OF_QL   = OF_QH   + (size_t)NTOK*HD;
constexpr size_t OF_KH   = OF_QL   + (size_t)NTOK*HD;
constexpr size_t OF_KL   = OF_KH   + (size_t)NTOK*HD;
constexpr size_t OF_VH   = OF_KL   + (size_t)NTOK*HD;
constexpr size_t OF_VL   = OF_VH   + (size_t)NTOK*HD;
constexpr size_t OF_AOH  = OF_VL   + (size_t)NTOK*HD;
constexpr size_t OF_AOL  = OF_AOH  + (size_t)NTOK*HD;
constexpr size_t BF_TOTAL= OF_AOL  + (size_t)NTOK*HD;

__device__ __nv_bfloat16 g_bf[BF_TOTAL];
__device__ float g_qr[NTOK * HEADS * DROPE];
__device__ float g_kr[NTOK * HEADS * DROPE];

// ---------------------------------------------------------------------------
// Helpers
// ---------------------------------------------------------------------------
__device__ __forceinline__ uint32_t smem_u32(const void* p) {
    uint32_t a;
    asm("{ .reg .u64 t; cvta.to.shared.u64 t, %1; cvt.u32.u64 %0, t; }"
        : "=r"(a) : "l"(p));
    return a;
}
__device__ __forceinline__ uint32_t packbf(float lo_elem, float hi_elem) {
    uint32_t r;
    asm("cvt.rn.bf16x2.f32 %0, %1, %2;" : "=r"(r) : "f"(hi_elem), "f"(lo_elem));
    return r;
}
__device__ __forceinline__ float bf16rt(float x) {
    __nv_bfloat16 h = __float2bfloat16(x);
    return __bfloat162float(h);
}
__device__ __forceinline__ void ldsm_x4(uint32_t& r0, uint32_t& r1, uint32_t& r2,
                                        uint32_t& r3, uint32_t addr) {
    asm volatile("ldmatrix.sync.aligned.m8n8.x4.shared.b16 {%0,%1,%2,%3}, [%4];"
                 : "=r"(r0), "=r"(r1), "=r"(r2), "=r"(r3) : "r"(addr));
}
__device__ __forceinline__ void ldsm_x4t(uint32_t& r0, uint32_t& r1, uint32_t& r2,
                                         uint32_t& r3, uint32_t addr) {
    asm volatile("ldmatrix.sync.aligned.m8n8.x4.trans.shared.b16 {%0,%1,%2,%3}, [%4];"
                 : "=r"(r0), "=r"(r1), "=r"(r2), "=r"(r3) : "r"(addr));
}
__device__ __forceinline__ void mma_bf16(float* d, const uint32_t* a, const uint32_t* b) {
    asm volatile(
        "mma.sync.aligned.m16n8k16.row.col.f32.bf16.bf16.f32 "
        "{%0,%1,%2,%3}, {%4,%5,%6,%7}, {%8,%9}, {%0,%1,%2,%3};"
        : "+f"(d[0]), "+f"(d[1]), "+f"(d[2]), "+f"(d[3])
        : "r"(a[0]), "r"(a[1]), "r"(a[2]), "r"(a[3]), "r"(b[0]), "r"(b[1]));
}
__device__ __forceinline__ void cp16(uint32_t saddr, const void* gaddr) {
    asm volatile("cp.async.cg.shared.global [%0], [%1], 16;" :: "r"(saddr), "l"(gaddr));
}
__device__ __forceinline__ void cp_commit() {
    asm volatile("cp.async.commit_group;" ::: "memory");
}
template<int N> __device__ __forceinline__ void cp_wait() {
    asm volatile("cp.async.wait_group %0;" :: "n"(N) : "memory");
}

// ---------------------------------------------------------------------------
// fp32 -> bf16 hi/lo split kernel
// ---------------------------------------------------------------------------
__global__ void split_kernel(const float* __restrict__ src,
                             __nv_bfloat16* __restrict__ hi,
                             __nv_bfloat16* __restrict__ lo, int n4)
{
    int i = blockIdx.x * blockDim.x + threadIdx.x;
    if (i >= n4) return;
    float4 v = ((const float4*)src)[i];
    float h0 = bf16rt(v.x), h1 = bf16rt(v.y), h2 = bf16rt(v.z), h3 = bf16rt(v.w);
    uint32_t* H = (uint32_t*)hi;
    uint32_t* L = (uint32_t*)lo;
    H[i*2]   = packbf(h0, h1);
    H[i*2+1] = packbf(h2, h3);
    L[i*2]   = packbf(v.x - h0, v.y - h1);
    L[i*2+1] = packbf(v.z - h2, v.w - h3);
}

// ---------------------------------------------------------------------------
// bf16-plane 3xBF16 GEMM: C = A*B (+bias)*scale.
// A planes [M][K] bf16, B planes [K][N] bf16. cp.async double-buffered.
// Outputs: optional fp32 Cf, optional bf16 hi/lo planes Ch/Cl, column remap.
// ---------------------------------------------------------------------------
#define BM 128
#define BN 128
#define BK 32
#define PA 40
#define PB 136
#define A_PLANE 10240
#define B_PLANE 8704
#define OFF_AHI 0
#define OFF_ALO (A_PLANE)
#define OFF_BHI (2*A_PLANE)
#define OFF_BLO (2*A_PLANE + B_PLANE)
#define SBUF    (2*A_PLANE + 2*B_PLANE)   // 37888
#define GSMEM   (2*SBUF)                  // 75776

__device__ __forceinline__ void gemm_issue(
    const __nv_bfloat16* Ah, const __nv_bfloat16* Al,
    const __nv_bfloat16* Bh, const __nv_bfloat16* Bl,
    int m0, int n0, int kk, int K, int N, uint32_t base, int t)
{
#pragma unroll
    for (int i = 0; i < 2; i++) {
        int f = t + i * 256;                  // 0..511
        int m = f >> 2, g = f & 3;
        size_t gi = (size_t)(m0 + m) * K + kk + g * 8;
        uint32_t so = (uint32_t)(m * 80 + g * 16);
        cp16(base + OFF_AHI + so, Ah + gi);
        cp16(base + OFF_ALO + so, Al + gi);
    }
#pragma unroll
    for (int i = 0; i < 2; i++) {
        int f = t + i * 256;
        int k2 = f >> 4, nc = f & 15;
        size_t gi = (size_t)(kk + k2) * N + n0 + nc * 8;
        uint32_t so = (uint32_t)(k2 * 272 + nc * 16);
        cp16(base + OFF_BHI + so, Bh + gi);
        cp16(base + OFF_BLO + so, Bl + gi);
    }
}

__global__ __launch_bounds__(256, 2)
void bf_gemm_kernel(const __nv_bfloat16* __restrict__ Ah, const __nv_bfloat16* __restrict__ Al,
                    const __nv_bfloat16* __restrict__ Bh, const __nv_bfloat16* __restrict__ Bl,
                    const float* __restrict__ bias,
                    float* __restrict__ Cf,
                    __nv_bfloat16* __restrict__ Ch, __nv_bfloat16* __restrict__ Cl,
                    int M, int N, int K,
                    int seg, int hstride, int col_off, int ostride, float scale)
{
    extern __shared__ char smc[];
    const uint32_t sb = smem_u32(smc);
    const int t    = threadIdx.x;
    const int lane = t & 31;
    const int w    = t >> 5;
    const int m0   = blockIdx.y * BM;
    const int n0   = blockIdx.x * BN;
    const int wm   = (w >> 2) * 64;
    const int wn   = (w & 3) * 32;

    float acc[4][4][4];
#pragma unroll
    for (int i = 0; i < 4; i++)
#pragma unroll
        for (int j = 0; j < 4; j++)
#pragma unroll
            for (int r = 0; r < 4; r++) acc[i][j][r] = 0.f;

    const uint32_t aLane = (uint32_t)((wm + (lane & 15)) * PA + (lane >> 4) * 8) * 2;
    const uint32_t bLaneRow = (uint32_t)(lane & 15) * PB * 2;
    const uint32_t bLaneCol = (uint32_t)(wn + (lane >> 4) * 8) * 2;

    const int NC = K / BK;

    gemm_issue(Ah, Al, Bh, Bl, m0, n0, 0, K, N, sb, t);
    cp_commit();

    for (int ch = 0; ch < NC; ch++) {
        if (ch + 1 < NC) {
            gemm_issue(Ah, Al, Bh, Bl, m0, n0, (ch + 1) * BK, K, N,
                       sb + (uint32_t)((ch + 1) & 1) * SBUF, t);
            cp_commit();
            cp_wait<1>();
        } else {
            cp_wait<0>();
        }
        __syncthreads();

        const uint32_t base = sb + (uint32_t)(ch & 1) * SBUF;
#pragma unroll
        for (int ks = 0; ks < 2; ks++) {
            uint32_t Ahf[4][4], Alf[4][4], Bhf[2][4], Blf[2][4];
            const uint32_t aOff = aLane + (uint32_t)ks * 32;
            const uint32_t bOff = bLaneRow + (uint32_t)ks * (16 * PB * 2);
#pragma unroll
            for (int mt = 0; mt < 4; mt++) {
                uint32_t ad = base + aOff + (uint32_t)mt * (16 * PA * 2);
                ldsm_x4(Ahf[mt][0], Ahf[mt][1], Ahf[mt][2], Ahf[mt][3], ad + OFF_AHI);
                ldsm_x4(Alf[mt][0], Alf[mt][1], Alf[mt][2], Alf[mt][3], ad + OFF_ALO);
            }
#pragma unroll
            for (int np = 0; np < 2; np++) {
                uint32_t bd = base + bOff + bLaneCol + (uint32_t)np * 32;
                ldsm_x4t(Bhf[np][0], Bhf[np][1], Bhf[np][2], Bhf[np][3], bd + OFF_BHI);
                ldsm_x4t(Blf[np][0], Blf[np][1], Blf[np][2], Blf[np][3], bd + OFF_BLO);
            }
#pragma unroll
            for (int mt = 0; mt < 4; mt++) {
#pragma unroll
                for (int nt = 0; nt < 4; nt++) {
                    const uint32_t* bh = &Bhf[nt >> 1][(nt & 1) * 2];
                    const uint32_t* bl = &Blf[nt >> 1][(nt & 1) * 2];
                    mma_bf16(acc[mt][nt], Ahf[mt], bh);
                    mma_bf16(acc[mt][nt], Ahf[mt], bl);
                    mma_bf16(acc[mt][nt], Alf[mt], bh);
                }
            }
        }
        __syncthreads();
    }

    // Epilogue
    const int r0 = lane >> 2;
    const int c0 = (lane & 3) * 2;
#pragma unroll
    for (int mt = 0; mt < 4; mt++) {
#pragma unroll
        for (int nt = 0; nt < 4; nt++) {
            int n = n0 + wn + nt * 8 + c0;
            int oc = (n / seg) * hstride + (n % seg) + col_off;
            float b0 = bias[n], b1 = bias[n + 1];
            int mrow0 = m0 + wm + mt * 16 + r0;
#pragma unroll
            for (int half = 0; half < 2; half++) {
                size_t row = (size_t)(mrow0 + half * 8);
                float v0 = (acc[mt][nt][half*2]   + b0) * scale;
                float v1 = (acc[mt][nt][half*2+1] + b1) * scale;
                if (Cf) *(float2*)&Cf[row * ostride + oc] = make_float2(v0, v1);
                if (Ch) {
                    float h0 = bf16rt(v0), h1 = bf16rt(v1);
                    *(uint32_t*)&Ch[row * ostride + oc] = packbf(h0, h1);
                    *(uint32_t*)&Cl[row * ostride + oc] = packbf(v0 - h0, v1 - h1);
                }
            }
        }
    }
}

// ---------------------------------------------------------------------------
// Rotary: reads fp32 pre-rotary q/k, writes k_rot fp32 output + scaled/split
// bf16 planes into Q/K cols 96..127.
// ---------------------------------------------------------------------------
__global__ void rotary_kernel(const float* __restrict__ qr,
                              const float* __restrict__ kr,
                              __nv_bfloat16* __restrict__ qh, __nv_bfloat16* __restrict__ ql,
                              __nv_bfloat16* __restrict__ kh, __nv_bfloat16* __restrict__ kl,
                              float* __restrict__ krot_out)
{
    int idx = blockIdx.x * blockDim.x + threadIdx.x;
    if (idx >= NTOK * HEADS) return;
    int h   = idx & (HEADS - 1);
    int tok = idx >> 4;
    int s   = tok & (SEQ - 1);
    float tpos = (float)s / 40.0f;
    const float qscale = 0.08838834764831845f;

    float xq[32], xk[32];
#pragma unroll
    for (int i = 0; i < 8; i++) {
        float4 a = *(const float4*)&qr[(size_t)idx * 32 + i * 4];
        xq[i*4+0]=a.x; xq[i*4+1]=a.y; xq[i*4+2]=a.z; xq[i*4+3]=a.w;
        float4 b = *(const float4*)&kr[(size_t)idx * 32 + i * 4];
        xk[i*4+0]=b.x; xk[i*4+1]=b.y; xk[i*4+2]=b.z; xk[i*4+3]=b.w;
    }

    float yq[32], yk[32];
#pragma unroll
    for (int j = 0; j < 8; j++) {
        float invf = exp2f(-1.6609640474436813f * (float)j);
        float ang = tpos * invf;
        float sj, cj;
        sincosf(ang, &sj, &cj);
        yq[j]     = xq[j] * cj - xq[j + 8] * sj;
        yq[j + 8] = xq[j + 8] * cj + xq[j] * sj;
        yk[j]     = xk[j] * cj - xk[j + 8] * sj;
        yk[j + 8] = xk[j + 8] * cj + xk[j] * sj;
    }
#pragma unroll
    for (int d = 16; d < 32; d++) { yq[d] = xq[d]; yk[d] = xk[d]; }

    size_t obase = (size_t)tok * HD + h * DHEAD + SPLIT;
#pragma unroll
    for (int j = 0; j < 16; j++) {
        float kv0 = yk[2*j], kv1 = yk[2*j+1];
        float kh0 = bf16rt(kv0), kh1 = bf16rt(kv1);
        *(uint32_t*)&kh[obase + 2*j] = packbf(kh0, kh1);
        *(uint32_t*)&kl[obase + 2*j] = packbf(kv0 - kh0, kv1 - kh1);
        float qv0 = yq[2*j] * qscale, qv1 = yq[2*j+1] * qscale;
        float qh0 = bf16rt(qv0), qh1 = bf16rt(qv1);
        *(uint32_t*)&qh[obase + 2*j] = packbf(qh0, qh1);
        *(uint32_t*)&ql[obase + 2*j] = packbf(qv0 - qh0, qv1 - qh1);
    }
#pragma unroll
    for (int i = 0; i < 8; i++) {
        *(float4*)&krot_out[(size_t)idx * 32 + i * 4] =
            make_float4(yk[i*4], yk[i*4+1], yk[i*4+2], yk[i*4+3]);
    }
}

// ---------------------------------------------------------------------------
// Causal flash-attention with 3xBF16 mma.sync, bf16-plane inputs via cp.async.
// CTA: 128 q-rows, one (b,h). 8 warps, each owns m16 slab. kt tiles of 64.
// K/V double-buffered. Output: ao bf16 hi/lo planes.
// ---------------------------------------------------------------------------
#define AM 128
#define AN 64
#define AD 128
#define APH 136
#define AQHI 0
#define AQLO (AM*APH*2)                  // 34816
#define AKV0 (2*AM*APH*2)                // 69632
#define KVP  (AN*APH*2)                  // 17408 per plane
#define KVBUF (4*KVP)                    // 69632 (Khi,Klo,Vhi,Vlo)
#define ASMEM (AKV0 + 2*KVBUF)           // 208896

__device__ __forceinline__ void attn_issue_kv(
    const __nv_bfloat16* kh, const __nv_bfloat16* kl,
    const __nv_bfloat16* vh, const __nv_bfloat16* vl,
    size_t rowbase, uint32_t kvbase, int t)
{
#pragma unroll
    for (int i = 0; i < 4; i++) {
        int f = t + i * 256;             // 0..1023
        int row = f >> 4, ch = f & 15;
        size_t gi = (rowbase + row) * HD + ch * 8;
        uint32_t so = (uint32_t)(row * 272 + ch * 16);
        cp16(kvbase + 0*KVP + so, kh + gi);
        cp16(kvbase + 1*KVP + so, kl + gi);
        cp16(kvbase + 2*KVP + so, vh + gi);
        cp16(kvbase + 3*KVP + so, vl + gi);
    }
}

__global__ __launch_bounds__(256, 1)
void attn_mma_kernel(const __nv_bfloat16* __restrict__ qh, const __nv_bfloat16* __restrict__ ql,
                     const __nv_bfloat16* __restrict__ kh, const __nv_bfloat16* __restrict__ kl,
                     const __nv_bfloat16* __restrict__ vh, const __nv_bfloat16* __restrict__ vl,
                     __nv_bfloat16* __restrict__ aoh, __nv_bfloat16* __restrict__ aol)
{
    extern __shared__ char smc[];
    const uint32_t sb = smem_u32(smc);
    const int t    = threadIdx.x;
    const int lane = t & 31;
    const int w    = t >> 5;
    const int bh   = blockIdx.y;
    const int b    = bh >> 4;
    const int h    = bh & 15;
    const int q0   = blockIdx.x * AM;

    // Q planes already scaled; head cols h*128..h*128+127
    const size_t qrowbase = (size_t)(b * SEQ + q0);
    const __nv_bfloat16* qhp = qh + h * DHEAD;
    const __nv_bfloat16* qlp = ql + h * DHEAD;
    const __nv_bfloat16* khp = kh + h * DHEAD;
    const __nv_bfloat16* klp = kl + h * DHEAD;
    const __nv_bfloat16* vhp = vh + h * DHEAD;
    const __nv_bfloat16* vlp = vl + h * DHEAD;

    // issue Q
#pragma unroll
    for (int i = 0; i < 8; i++) {
        int f = t + i * 256;             // 0..2047
        int row = f >> 4, ch = f & 15;
        size_t gi = (qrowbase + row) * HD + ch * 8;
        uint32_t so = (uint32_t)(row * 272 + ch * 16);
        cp16(sb + AQHI + so, qhp + gi);
        cp16(sb + AQLO + so, qlp + gi);
    }
    // issue KV tile 0
    attn_issue_kv(khp, klp, vhp, vlp, (size_t)(b * SEQ), sb + AKV0, t);
    cp_commit();

    float mrow[2] = {-INFINITY, -INFINITY};
    float lrow[2] = {0.f, 0.f};
    float O[16][4];
#pragma unroll
    for (int i = 0; i < 16; i++)
#pragma unroll
        for (int r = 0; r < 4; r++) O[i][r] = 0.f;

    const int ntiles = q0 / AN + 2;
    for (int nt = 0; nt < ntiles; nt++) {
        const int n0 = nt * AN;
        if (nt + 1 < ntiles) {
            attn_issue_kv(khp, klp, vhp, vlp, (size_t)(b * SEQ + (nt + 1) * AN),
                          sb + AKV0 + (uint32_t)((nt + 1) & 1) * KVBUF, t);
            cp_commit();
            cp_wait<1>();
        } else {
            cp_wait<0>();
        }
        __syncthreads();

        const uint32_t kvb = sb + AKV0 + (uint32_t)(nt & 1) * KVBUF;
        const bool active = (q0 + w * 16 + 15) >= n0;
        if (active) {
            // ---- S = Q K^T ----
            float S[8][4];
#pragma unroll
            for (int nf = 0; nf < 8; nf++)
#pragma unroll
                for (int r = 0; r < 4; r++) S[nf][r] = 0.f;

#pragma unroll
            for (int ks = 0; ks < 8; ks++) {
                uint32_t ah[4], al[4];
                uint32_t ad = sb + (uint32_t)((w * 16 + (lane & 15)) * APH
                                              + ks * 16 + (lane >> 4) * 8) * 2;
                ldsm_x4(ah[0], ah[1], ah[2], ah[3], ad + AQHI);
                ldsm_x4(al[0], al[1], al[2], al[3], ad + AQLO);
#pragma unroll
                for (int g = 0; g < 4; g++) {
                    uint32_t bd = kvb + (uint32_t)((g * 16 + (lane & 7) + (lane >> 4) * 8) * APH
                                                   + ks * 16 + ((lane >> 3) & 1) * 8) * 2;
                    uint32_t khf[4], klf[4];
                    ldsm_x4(khf[0], khf[1], khf[2], khf[3], bd + 0*KVP);
                    ldsm_x4(klf[0], klf[1], klf[2], klf[3], bd + 1*KVP);
                    mma_bf16(S[2*g],   ah, &khf[0]);
                    mma_bf16(S[2*g],   ah, &klf[0]);
                    mma_bf16(S[2*g],   al, &khf[0]);
                    mma_bf16(S[2*g+1], ah, &khf[2]);
                    mma_bf16(S[2*g+1], ah, &klf[2]);
                    mma_bf16(S[2*g+1], al, &khf[2]);
                }
            }

            // ---- causal mask ----
            if (n0 + AN - 1 > q0 + w * 16) {
                int grow0 = q0 + w * 16 + (lane >> 2);
#pragma unroll
                for (int nf = 0; nf < 8; nf++) {
                    int col = n0 + nf * 8 + (lane & 3) * 2;
#pragma unroll
                    for (int r = 0; r < 4; r++) {
                        int gr = grow0 + (r >> 1) * 8;
                        int gc = col + (r & 1);
                        if (gc > gr) S[nf][r] = -INFINITY;
                    }
                }
            }

            // ---- online softmax ----
            float corr[2];
#pragma unroll
            for (int rr = 0; rr < 2; rr++) {
                float rm = -INFINITY;
#pragma unroll
                for (int nf = 0; nf < 8; nf++)
                    rm = fmaxf(rm, fmaxf(S[nf][rr*2], S[nf][rr*2+1]));
                rm = fmaxf(rm, __shfl_xor_sync(0xffffffffu, rm, 1));
                rm = fmaxf(rm, __shfl_xor_sync(0xffffffffu, rm, 2));
                float mnew = fmaxf(mrow[rr], rm);
                corr[rr] = __expf(mrow[rr] - mnew);
                float rs = 0.f;
#pragma unroll
                for (int nf = 0; nf < 8; nf++) {
                    float p0 = __expf(S[nf][rr*2]   - mnew);
                    float p1 = __expf(S[nf][rr*2+1] - mnew);
                    S[nf][rr*2]   = p0;
                    S[nf][rr*2+1] = p1;
                    rs += p0 + p1;
                }
                rs += __shfl_xor_sync(0xffffffffu, rs, 1);
                rs += __shfl_xor_sync(0xffffffffu, rs, 2);
                lrow[rr] = lrow[rr] * corr[rr] + rs;
                mrow[rr] = mnew;
            }
#pragma unroll
            for (int i = 0; i < 16; i++) {
                O[i][0] *= corr[0]; O[i][1] *= corr[0];
                O[i][2] *= corr[1]; O[i][3] *= corr[1];
            }

            // ---- O += P V ----
#pragma unroll
            for (int j = 0; j < 4; j++) {
                uint32_t ph[4], pl[4];
                {
                    float s00 = S[2*j][0],   s01 = S[2*j][1],   s02 = S[2*j][2],   s03 = S[2*j][3];
                    float s10 = S[2*j+1][0], s11 = S[2*j+1][1], s12 = S[2*j+1][2], s13 = S[2*j+1][3];
                    float h00 = bf16rt(s00), h01 = bf16rt(s01), h02 = bf16rt(s02), h03 = bf16rt(s03);
                    float h10 = bf16rt(s10), h11 = bf16rt(s11), h12 = bf16rt(s12), h13 = bf16rt(s13);
                    ph[0] = packbf(h00, h01); ph[1] = packbf(h02, h03);
                    ph[2] = packbf(h10, h11); ph[3] = packbf(h12, h13);
                    pl[0] = packbf(s00 - h00, s01 - h01); pl[1] = packbf(s02 - h02, s03 - h03);
                    pl[2] = packbf(s10 - h10, s11 - h11); pl[3] = packbf(s12 - h12, s13 - h13);
                }
#pragma unroll
                for (int g = 0; g < 8; g++) {
                    uint32_t vd = kvb + (uint32_t)((j * 16 + (lane & 15)) * APH
                                                   + g * 16 + (lane >> 4) * 8) * 2;
                    uint32_t vhf[4], vlf[4];
                    ldsm_x4t(vhf[0], vhf[1], vhf[2], vhf[3], vd + 2*KVP);
                    ldsm_x4t(vlf[0], vlf[1], vlf[2], vlf[3], vd + 3*KVP);
                    mma_bf16(O[2*g],   ph, &vhf[0]);
                    mma_bf16(O[2*g],   ph, &vlf[0]);
                    mma_bf16(O[2*g],   pl, &vhf[0]);
                    mma_bf16(O[2*g+1], ph, &vhf[2]);
                    mma_bf16(O[2*g+1], ph, &vlf[2]);
                    mma_bf16(O[2*g+1], pl, &vhf[2]);
                }
            }
        }
        __syncthreads();
    }

    // ---- epilogue: write ao bf16 hi/lo planes ----
    float inv0 = 1.0f / lrow[0];
    float inv1 = 1.0f / lrow[1];
#pragma unroll
    for (int nd = 0; nd < 16; nd++) {
        int d = nd * 8 + (lane & 3) * 2;
        size_t row0 = (size_t)(b * SEQ + q0 + w * 16 + (lane >> 2));
        float v0 = O[nd][0] * inv0, v1 = O[nd][1] * inv0;
        float h0 = bf16rt(v0), h1 = bf16rt(v1);
        *(uint32_t*)&aoh[row0 * HD + h * DHEAD + d] = packbf(h0, h1);
        *(uint32_t*)&aol[row0 * HD + h * DHEAD + d] = packbf(v0 - h0, v1 - h1);
        float v2 = O[nd][2] * inv1, v3 = O[nd][3] * inv1;
        float h2 = bf16rt(v2), h3 = bf16rt(v3);
        *(uint32_t*)&aoh[(row0 + 8) * HD + h * DHEAD + d] = packbf(h2, h3);
        *(uint32_t*)&aol[(row0 + 8) * HD + h * DHEAD + d] = packbf(v2 - h2, v3 - h3);
    }
}

// ---------------------------------------------------------------------------
// Launcher
// ---------------------------------------------------------------------------
extern "C" void kernel_launch(void* const* d_in, const int* in_sizes, int n_in,
                              void* d_out, int out_size)
{
    (void)in_sizes; (void)n_in; (void)out_size;

    const float* h_in   = (const float*)d_in[0];
    const float* W_dkv  = (const float*)d_in[1];
    const float* b_dkv  = (const float*)d_in[2];
    const float* W_dq   = (const float*)d_in[3];
    const float* b_dq   = (const float*)d_in[4];
    const float* W_uk   = (const float*)d_in[5];
    const float* b_uk   = (const float*)d_in[6];
    const float* W_uv   = (const float*)d_in[7];
    const float* b_uv   = (const float*)d_in[8];
    const float* W_uq   = (const float*)d_in[9];
    const float* b_uq   = (const float*)d_in[10];
    const float* W_qr   = (const float*)d_in[11];
    const float* b_qr   = (const float*)d_in[12];
    const float* W_kr   = (const float*)d_in[13];
    const float* b_kr   = (const float*)d_in[14];
    const float* W_out  = (const float*)d_in[15];
    const float* b_out  = (const float*)d_in[16];

    float* out_main = (float*)d_out;
    float* out_ckv  = out_main + (size_t)NTOK * EMB;
    float* out_krot = out_ckv + (size_t)NTOK * CLAT;

    __nv_bfloat16* bf;
    float *p_qr, *p_kr;
    cudaGetSymbolAddress((void**)&bf, g_bf);
    cudaGetSymbolAddress((void**)&p_qr, g_qr);
    cudaGetSymbolAddress((void**)&p_kr, g_kr);

    cudaFuncSetAttribute(bf_gemm_kernel, cudaFuncAttributeMaxDynamicSharedMemorySize, GSMEM);
    cudaFuncSetAttribute(attn_mma_kernel, cudaFuncAttributeMaxDynamicSharedMemorySize, ASMEM);

    dim3 thr(256);
    const int M = NTOK;

    // --- split conversions: h + all weights ---
    auto split = [&](const float* src, size_t offH, size_t offL, size_t n) {
        int n4 = (int)(n / 4);
        split_kernel<<<(n4 + 255) / 256, 256>>>(src, bf + offH, bf + offL, n4);
    };
    split(h_in,  OF_HH,   OF_HL,   (size_t)NTOK * EMB);
    split(W_dkv, OF_DKVH, OF_DKVL, (size_t)EMB * CLAT);
    split(W_dq,  OF_DQH,  OF_DQL,  (size_t)EMB * CLAT);
    split(W_kr,  OF_KRH,  OF_KRL,  (size_t)EMB * (HEADS * DROPE));
    split(W_uk,  OF_UKH,  OF_UKL,  (size_t)CLAT * (HEADS * SPLIT));
    split(W_uv,  OF_UVH,  OF_UVL,  (size_t)CLAT * HD);
    split(W_uq,  OF_UQH,  OF_UQL,  (size_t)CLAT * (HEADS * SPLIT));
    split(W_qr,  OF_QRH,  OF_QRL,  (size_t)CLAT * (HEADS * DROPE));
    split(W_out, OF_OUTH, OF_OUTL, (size_t)HD * EMB);

    const float qsc = 0.08838834764831845f;

    // 1. c_kv = h @ W_dkv  -> fp32 output region + planes
    bf_gemm_kernel<<<dim3(CLAT/BN, M/BM), thr, GSMEM>>>(
        bf+OF_HH, bf+OF_HL, bf+OF_DKVH, bf+OF_DKVL, b_dkv,
        out_ckv, bf+OF_CKVH, bf+OF_CKVL,
        M, CLAT, EMB, CLAT, CLAT, 0, CLAT, 1.0f);
    // 2. c_q -> planes only
    bf_gemm_kernel<<<dim3(CLAT/BN, M/BM), thr, GSMEM>>>(
        bf+OF_HH, bf+OF_HL, bf+OF_DQH, bf+OF_DQL, b_dq,
        nullptr, bf+OF_CQH, bf+OF_CQL,
        M, CLAT, EMB, CLAT, CLAT, 0, CLAT, 1.0f);
    // 3. k_rot_pre -> fp32
    bf_gemm_kernel<<<dim3((HEADS*DROPE)/BN, M/BM), thr, GSMEM>>>(
        bf+OF_HH, bf+OF_HL, bf+OF_KRH, bf+OF_KRL, b_kr,
        p_kr, nullptr, nullptr,
        M, HEADS*DROPE, EMB, HEADS*DROPE, HEADS*DROPE, 0, HEADS*DROPE, 1.0f);
    // 4. k_base -> K planes cols h*128+0..95
    bf_gemm_kernel<<<dim3((HEADS*SPLIT)/BN, M/BM), thr, GSMEM>>>(
        bf+OF_CKVH, bf+OF_CKVL, bf+OF_UKH, bf+OF_UKL, b_uk,
        nullptr, bf+OF_KH, bf+OF_KL,
        M, HEADS*SPLIT, CLAT, SPLIT, DHEAD, 0, HD, 1.0f);
    // 5. v -> V planes
    bf_gemm_kernel<<<dim3(HD/BN, M/BM), thr, GSMEM>>>(
        bf+OF_CKVH, bf+OF_CKVL, bf+OF_UVH, bf+OF_UVL, b_uv,
        nullptr, bf+OF_VH, bf+OF_VL,
        M, HD, CLAT, HD, HD, 0, HD, 1.0f);
    // 6. q_base -> Q planes (pre-scaled)
    bf_gemm_kernel<<<dim3((HEADS*SPLIT)/BN, M/BM), thr, GSMEM>>>(
        bf+OF_CQH, bf+OF_CQL, bf+OF_UQH, bf+OF_UQL, b_uq,
        nullptr, bf+OF_QH, bf+OF_QL,
        M, HEADS*SPLIT, CLAT, SPLIT, DHEAD, 0, HD, qsc);
    // 7. q_rot_pre -> fp32
    bf_gemm_kernel<<<dim3((HEADS*DROPE)/BN, M/BM), thr, GSMEM>>>(
        bf+OF_CQH, bf+OF_CQL, bf+OF_QRH, bf+OF_QRL, b_qr,
        p_qr, nullptr, nullptr,
        M, HEADS*DROPE, CLAT, HEADS*DROPE, HEADS*DROPE, 0, HEADS*DROPE, 1.0f);
    // 8. rotary -> k_rot fp32 out + Q/K plane cols 96..127
    rotary_kernel<<<(NTOK*HEADS + 255)/256, 256>>>(
        p_qr, p_kr, bf+OF_QH, bf+OF_QL, bf+OF_KH, bf+OF_KL, out_krot);
    // 9. attention -> ao planes
    attn_mma_kernel<<<dim3(SEQ/AM, BATCH*HEADS), thr, ASMEM>>>(
        bf+OF_QH, bf+OF_QL, bf+OF_KH, bf+OF_KL, bf+OF_VH, bf+OF_VL,
        bf+OF_AOH, bf+OF_AOL);
    // 10. out = ao @ W_out + b_out -> fp32 main output
    bf_gemm_kernel<<<dim3(EMB/BN, M/BM), thr, GSMEM>>>(
        bf+OF_AOH, bf+OF_AOL, bf+OF_OUTH, bf+OF_OUTL, b_out,
        out_main, nullptr, nullptr,
        M, EMB, HD, EMB, EMB, 0, EMB, 1.0f);
}